// round 8
// baseline (speedup 1.0000x reference)
#include <cuda_runtime.h>
#include <cuda_bf16.h>
#include <math.h>

#define N_NODES 100000
#define D 128

// Scratch: ping-pong node-feature buffers (static __device__ per allocation rules)
__device__ float g_bufA[(size_t)N_NODES * D];
__device__ float g_bufB[(size_t)N_NODES * D];

// ---------------------------------------------------------------------------
// Zero a float buffer (grid-stride, float4)
// ---------------------------------------------------------------------------
__global__ void zero_kernel(float* __restrict__ buf, int n4) {
    int idx = blockIdx.x * blockDim.x + threadIdx.x;
    int stride = gridDim.x * blockDim.x;
    float4 z = make_float4(0.f, 0.f, 0.f, 0.f);
    for (int i = idx; i < n4; i += stride)
        reinterpret_cast<float4*>(buf)[i] = z;
}

// ---------------------------------------------------------------------------
// SpMM: out[row[e]] += val[e] * x[col[e]]   (one warp per edge, float4 lanes)
// ---------------------------------------------------------------------------
__global__ __launch_bounds__(256) void spmm_kernel(
    const int* __restrict__ erow, const int* __restrict__ ecol,
    const float* __restrict__ eval, const float* __restrict__ x,
    float* __restrict__ out, int nE)
{
    int gtid = blockIdx.x * blockDim.x + threadIdx.x;
    int e = gtid >> 5;
    int lane = gtid & 31;
    if (e >= nE) return;

    int r = __ldg(erow + e);
    int c = __ldg(ecol + e);
    float v = __ldg(eval + e);

    const float4 xv = *reinterpret_cast<const float4*>(x + (size_t)c * D + lane * 4);
    float a0 = xv.x * v, a1 = xv.y * v, a2 = xv.z * v, a3 = xv.w * v;

    float* dst = out + (size_t)r * D + lane * 4;
    asm volatile("red.global.add.v4.f32 [%0], {%1, %2, %3, %4};"
                 :: "l"(dst), "f"(a0), "f"(a1), "f"(a2), "f"(a3)
                 : "memory");
}

// ---------------------------------------------------------------------------
// C[M,128] = relu(A[M,128] @ W[128,128] + b)
// Block: 256 threads, tile 64 rows x 128 cols, per-thread 4x8 micro-tile.
// ---------------------------------------------------------------------------
#define BM 64
#define BK 32
#define AS_LD (BK + 1)

__global__ __launch_bounds__(256) void gemm_bias_relu_kernel(
    const float* __restrict__ A, const float* __restrict__ W,
    const float* __restrict__ bias, float* __restrict__ C, int M)
{
    __shared__ float As[BM * AS_LD];    // padded: kills bank conflicts on broadcast pairs
    __shared__ float Ws[BK * D];

    const int tid = threadIdx.x;
    const int tx = tid & 15;            // col group -> cols [tx*8, tx*8+8)
    const int ty = tid >> 4;            // row group -> rows [ty*4, ty*4+4)
    const int row0 = blockIdx.x * BM;

    float acc[4][8];
    #pragma unroll
    for (int i = 0; i < 4; i++)
        #pragma unroll
        for (int j = 0; j < 8; j++) acc[i][j] = 0.f;

    for (int k0 = 0; k0 < D; k0 += BK) {
        // Stage A tile [BM x BK] (row-major source, padded smem)
        #pragma unroll
        for (int i = 0; i < 2; i++) {
            int fid = tid + i * 256;        // 512 float4 loads total
            int m   = fid >> 3;             // 8 float4 per row of 32
            int kk  = (fid & 7) << 2;
            int gr  = row0 + m;
            float4 v = make_float4(0.f, 0.f, 0.f, 0.f);
            if (gr < M)
                v = *reinterpret_cast<const float4*>(A + (size_t)gr * D + k0 + kk);
            float* s = As + m * AS_LD + kk;
            s[0] = v.x; s[1] = v.y; s[2] = v.z; s[3] = v.w;
        }
        // Stage W tile [BK x 128]
        #pragma unroll
        for (int i = 0; i < 4; i++) {
            int fid = tid + i * 256;        // 1024 float4 loads total
            int k   = fid >> 5;
            int n4  = (fid & 31) << 2;
            *reinterpret_cast<float4*>(Ws + k * D + n4) =
                *reinterpret_cast<const float4*>(W + (size_t)(k0 + k) * D + n4);
        }
        __syncthreads();

        #pragma unroll
        for (int kk = 0; kk < BK; kk++) {
            float a[4];
            #pragma unroll
            for (int i = 0; i < 4; i++)
                a[i] = As[(ty * 4 + i) * AS_LD + kk];
            const float4 w0 = *reinterpret_cast<const float4*>(Ws + kk * D + tx * 8);
            const float4 w1 = *reinterpret_cast<const float4*>(Ws + kk * D + tx * 8 + 4);
            #pragma unroll
            for (int i = 0; i < 4; i++) {
                acc[i][0] += a[i] * w0.x;
                acc[i][1] += a[i] * w0.y;
                acc[i][2] += a[i] * w0.z;
                acc[i][3] += a[i] * w0.w;
                acc[i][4] += a[i] * w1.x;
                acc[i][5] += a[i] * w1.y;
                acc[i][6] += a[i] * w1.z;
                acc[i][7] += a[i] * w1.w;
            }
        }
        __syncthreads();
    }

    const float4 b0 = *reinterpret_cast<const float4*>(bias + tx * 8);
    const float4 b1 = *reinterpret_cast<const float4*>(bias + tx * 8 + 4);
    #pragma unroll
    for (int i = 0; i < 4; i++) {
        int gr = row0 + ty * 4 + i;
        if (gr >= M) continue;
        float4 o0, o1;
        o0.x = fmaxf(acc[i][0] + b0.x, 0.f);
        o0.y = fmaxf(acc[i][1] + b0.y, 0.f);
        o0.z = fmaxf(acc[i][2] + b0.z, 0.f);
        o0.w = fmaxf(acc[i][3] + b0.w, 0.f);
        o1.x = fmaxf(acc[i][4] + b1.x, 0.f);
        o1.y = fmaxf(acc[i][5] + b1.y, 0.f);
        o1.z = fmaxf(acc[i][6] + b1.z, 0.f);
        o1.w = fmaxf(acc[i][7] + b1.w, 0.f);
        *reinterpret_cast<float4*>(C + (size_t)gr * D + tx * 8)     = o0;
        *reinterpret_cast<float4*>(C + (size_t)gr * D + tx * 8 + 4) = o1;
    }
}

// ---------------------------------------------------------------------------
// out[n] = softplus(dot(H[n], Wout) + bout)  — one warp per row
// ---------------------------------------------------------------------------
__global__ __launch_bounds__(256) void head_kernel(
    const float* __restrict__ H, const float* __restrict__ Wout,
    const float* __restrict__ bout, float* __restrict__ out, int M)
{
    int gtid = blockIdx.x * blockDim.x + threadIdx.x;
    int r = gtid >> 5;
    int lane = gtid & 31;
    if (r >= M) return;

    const float4 h = *reinterpret_cast<const float4*>(H + (size_t)r * D + lane * 4);
    const float4 w = *reinterpret_cast<const float4*>(Wout + lane * 4);
    float s = h.x * w.x + h.y * w.y + h.z * w.z + h.w * w.w;
    #pragma unroll
    for (int o = 16; o > 0; o >>= 1)
        s += __shfl_xor_sync(0xFFFFFFFFu, s, o);
    if (lane == 0) {
        s += bout[0];
        // softplus = logaddexp(s, 0) = max(s,0) + log1p(exp(-|s|))
        out[r] = fmaxf(s, 0.f) + log1pf(expf(-fabsf(s)));
    }
}

// ---------------------------------------------------------------------------
// Launch
// ---------------------------------------------------------------------------
extern "C" void kernel_launch(void* const* d_in, const int* in_sizes, int n_in,
                              void* d_out, int out_size)
{
    const float* x     = (const float*)d_in[0];
    const int*   erow  = (const int*)  d_in[1];
    const int*   ecol  = (const int*)  d_in[2];
    const float* eval  = (const float*)d_in[3];
    const float* W1    = (const float*)d_in[4];
    const float* b1    = (const float*)d_in[5];
    const float* W2    = (const float*)d_in[6];
    const float* b2    = (const float*)d_in[7];
    const float* Wout  = (const float*)d_in[8];
    const float* bout  = (const float*)d_in[9];
    float* out = (float*)d_out;

    const int M  = in_sizes[0] / D;     // 100000
    const int nE = in_sizes[1];         // 1600000

    float* bufA;
    float* bufB;
    cudaGetSymbolAddress((void**)&bufA, g_bufA);
    cudaGetSymbolAddress((void**)&bufB, g_bufB);

    const int n4 = (M * D) / 4;
    const int zeroBlocks = 2048;
    const int spmmBlocks = (nE * 32 + 255) / 256;
    const int gemmBlocks = (M + BM - 1) / BM;
    const int headBlocks = (M * 32 + 255) / 256;

    // Layer 1: h = relu(spmm(x) @ W1 + b1)
    zero_kernel<<<zeroBlocks, 256>>>(bufA, n4);
    spmm_kernel<<<spmmBlocks, 256>>>(erow, ecol, eval, x, bufA, nE);
    gemm_bias_relu_kernel<<<gemmBlocks, 256>>>(bufA, W1, b1, bufB, M);

    // Layer 2: h = relu(spmm(h) @ W2 + b2)
    zero_kernel<<<zeroBlocks, 256>>>(bufA, n4);
    spmm_kernel<<<spmmBlocks, 256>>>(erow, ecol, eval, bufB, bufA, nE);
    gemm_bias_relu_kernel<<<gemmBlocks, 256>>>(bufA, W2, b2, bufB, M);

    // Final aggregation + head
    zero_kernel<<<zeroBlocks, 256>>>(bufA, n4);
    spmm_kernel<<<spmmBlocks, 256>>>(erow, ecol, eval, bufB, bufA, nE);
    head_kernel<<<headBlocks, 256>>>(bufA, Wout, bout, out, M);
}

// round 9
// speedup vs baseline: 1.0143x; 1.0143x over previous
#include <cuda_runtime.h>
#include <cuda_bf16.h>
#include <math.h>

#define N_NODES 100000
#define D 128

// Scratch: ping-pong node-feature buffers (static __device__ per allocation rules)
__device__ float g_bufA[(size_t)N_NODES * D];
__device__ float g_bufB[(size_t)N_NODES * D];

// ---------------------------------------------------------------------------
// Zero a float buffer (grid-stride, float4)
// ---------------------------------------------------------------------------
__global__ void zero_kernel(float* __restrict__ buf, int n4) {
    int idx = blockIdx.x * blockDim.x + threadIdx.x;
    int stride = gridDim.x * blockDim.x;
    float4 z = make_float4(0.f, 0.f, 0.f, 0.f);
    for (int i = idx; i < n4; i += stride)
        reinterpret_cast<float4*>(buf)[i] = z;
}

// ---------------------------------------------------------------------------
// SpMM: out[row[e]] += val[e] * x[col[e]]   (one warp per edge, float4 lanes)
// ---------------------------------------------------------------------------
__global__ __launch_bounds__(256) void spmm_kernel(
    const int* __restrict__ erow, const int* __restrict__ ecol,
    const float* __restrict__ eval, const float* __restrict__ x,
    float* __restrict__ out, int nE)
{
    int gtid = blockIdx.x * blockDim.x + threadIdx.x;
    int e = gtid >> 5;
    int lane = gtid & 31;
    if (e >= nE) return;

    int r = __ldg(erow + e);
    int c = __ldg(ecol + e);
    float v = __ldg(eval + e);

    const float4 xv = *reinterpret_cast<const float4*>(x + (size_t)c * D + lane * 4);
    float a0 = xv.x * v, a1 = xv.y * v, a2 = xv.z * v, a3 = xv.w * v;

    float* dst = out + (size_t)r * D + lane * 4;
    asm volatile("red.global.add.v4.f32 [%0], {%1, %2, %3, %4};"
                 :: "l"(dst), "f"(a0), "f"(a1), "f"(a2), "f"(a3)
                 : "memory");
}

// ---------------------------------------------------------------------------
// C[M,128] = relu(A[M,128] @ W[128,128] + b)
// Block: 256 threads, tile 64 rows x 128 cols, per-thread 4x8 micro-tile.
// ---------------------------------------------------------------------------
#define BM 64
#define BK 32
#define AS_LD (BK + 1)

__global__ __launch_bounds__(256) void gemm_bias_relu_kernel(
    const float* __restrict__ A, const float* __restrict__ W,
    const float* __restrict__ bias, float* __restrict__ C, int M)
{
    __shared__ float As[BM * AS_LD];    // padded: kills bank conflicts on broadcast pairs
    __shared__ float Ws[BK * D];

    const int tid = threadIdx.x;
    const int tx = tid & 15;            // col group -> cols [tx*8, tx*8+8)
    const int ty = tid >> 4;            // row group -> rows [ty*4, ty*4+4)
    const int row0 = blockIdx.x * BM;

    float acc[4][8];
    #pragma unroll
    for (int i = 0; i < 4; i++)
        #pragma unroll
        for (int j = 0; j < 8; j++) acc[i][j] = 0.f;

    for (int k0 = 0; k0 < D; k0 += BK) {
        // Stage A tile [BM x BK] (row-major source, padded smem)
        #pragma unroll
        for (int i = 0; i < 2; i++) {
            int fid = tid + i * 256;        // 512 float4 loads total
            int m   = fid >> 3;             // 8 float4 per row of 32
            int kk  = (fid & 7) << 2;
            int gr  = row0 + m;
            float4 v = make_float4(0.f, 0.f, 0.f, 0.f);
            if (gr < M)
                v = *reinterpret_cast<const float4*>(A + (size_t)gr * D + k0 + kk);
            float* s = As + m * AS_LD + kk;
            s[0] = v.x; s[1] = v.y; s[2] = v.z; s[3] = v.w;
        }
        // Stage W tile [BK x 128]
        #pragma unroll
        for (int i = 0; i < 4; i++) {
            int fid = tid + i * 256;        // 1024 float4 loads total
            int k   = fid >> 5;
            int n4  = (fid & 31) << 2;
            *reinterpret_cast<float4*>(Ws + k * D + n4) =
                *reinterpret_cast<const float4*>(W + (size_t)(k0 + k) * D + n4);
        }
        __syncthreads();

        #pragma unroll
        for (int kk = 0; kk < BK; kk++) {
            float a[4];
            #pragma unroll
            for (int i = 0; i < 4; i++)
                a[i] = As[(ty * 4 + i) * AS_LD + kk];
            const float4 w0 = *reinterpret_cast<const float4*>(Ws + kk * D + tx * 8);
            const float4 w1 = *reinterpret_cast<const float4*>(Ws + kk * D + tx * 8 + 4);
            #pragma unroll
            for (int i = 0; i < 4; i++) {
                acc[i][0] += a[i] * w0.x;
                acc[i][1] += a[i] * w0.y;
                acc[i][2] += a[i] * w0.z;
                acc[i][3] += a[i] * w0.w;
                acc[i][4] += a[i] * w1.x;
                acc[i][5] += a[i] * w1.y;
                acc[i][6] += a[i] * w1.z;
                acc[i][7] += a[i] * w1.w;
            }
        }
        __syncthreads();
    }

    const float4 b0 = *reinterpret_cast<const float4*>(bias + tx * 8);
    const float4 b1 = *reinterpret_cast<const float4*>(bias + tx * 8 + 4);
    #pragma unroll
    for (int i = 0; i < 4; i++) {
        int gr = row0 + ty * 4 + i;
        if (gr >= M) continue;
        float4 o0, o1;
        o0.x = fmaxf(acc[i][0] + b0.x, 0.f);
        o0.y = fmaxf(acc[i][1] + b0.y, 0.f);
        o0.z = fmaxf(acc[i][2] + b0.z, 0.f);
        o0.w = fmaxf(acc[i][3] + b0.w, 0.f);
        o1.x = fmaxf(acc[i][4] + b1.x, 0.f);
        o1.y = fmaxf(acc[i][5] + b1.y, 0.f);
        o1.z = fmaxf(acc[i][6] + b1.z, 0.f);
        o1.w = fmaxf(acc[i][7] + b1.w, 0.f);
        *reinterpret_cast<float4*>(C + (size_t)gr * D + tx * 8)     = o0;
        *reinterpret_cast<float4*>(C + (size_t)gr * D + tx * 8 + 4) = o1;
    }
}

// ---------------------------------------------------------------------------
// out[n] = softplus(dot(H[n], Wout) + bout)  — one warp per row
// ---------------------------------------------------------------------------
__global__ __launch_bounds__(256) void head_kernel(
    const float* __restrict__ H, const float* __restrict__ Wout,
    const float* __restrict__ bout, float* __restrict__ out, int M)
{
    int gtid = blockIdx.x * blockDim.x + threadIdx.x;
    int r = gtid >> 5;
    int lane = gtid & 31;
    if (r >= M) return;

    const float4 h = *reinterpret_cast<const float4*>(H + (size_t)r * D + lane * 4);
    const float4 w = *reinterpret_cast<const float4*>(Wout + lane * 4);
    float s = h.x * w.x + h.y * w.y + h.z * w.z + h.w * w.w;
    #pragma unroll
    for (int o = 16; o > 0; o >>= 1)
        s += __shfl_xor_sync(0xFFFFFFFFu, s, o);
    if (lane == 0) {
        s += bout[0];
        // softplus = logaddexp(s, 0) = max(s,0) + log1p(exp(-|s|))
        out[r] = fmaxf(s, 0.f) + log1pf(expf(-fabsf(s)));
    }
}

// ---------------------------------------------------------------------------
// Launch
// ---------------------------------------------------------------------------
extern "C" void kernel_launch(void* const* d_in, const int* in_sizes, int n_in,
                              void* d_out, int out_size)
{
    const float* x     = (const float*)d_in[0];
    const int*   erow  = (const int*)  d_in[1];
    const int*   ecol  = (const int*)  d_in[2];
    const float* eval  = (const float*)d_in[3];
    const float* W1    = (const float*)d_in[4];
    const float* b1    = (const float*)d_in[5];
    const float* W2    = (const float*)d_in[6];
    const float* b2    = (const float*)d_in[7];
    const float* Wout  = (const float*)d_in[8];
    const float* bout  = (const float*)d_in[9];
    float* out = (float*)d_out;

    const int M  = in_sizes[0] / D;     // 100000
    const int nE = in_sizes[1];         // 1600000

    float* bufA;
    float* bufB;
    cudaGetSymbolAddress((void**)&bufA, g_bufA);
    cudaGetSymbolAddress((void**)&bufB, g_bufB);

    const int n4 = (M * D) / 4;
    const int zeroBlocks = 2048;
    const int spmmBlocks = (nE * 32 + 255) / 256;
    const int gemmBlocks = (M + BM - 1) / BM;
    const int headBlocks = (M * 32 + 255) / 256;

    // Layer 1: h = relu(spmm(x) @ W1 + b1)
    zero_kernel<<<zeroBlocks, 256>>>(bufA, n4);
    spmm_kernel<<<spmmBlocks, 256>>>(erow, ecol, eval, x, bufA, nE);
    gemm_bias_relu_kernel<<<gemmBlocks, 256>>>(bufA, W1, b1, bufB, M);

    // Layer 2: h = relu(spmm(h) @ W2 + b2)
    zero_kernel<<<zeroBlocks, 256>>>(bufA, n4);
    spmm_kernel<<<spmmBlocks, 256>>>(erow, ecol, eval, bufB, bufA, nE);
    gemm_bias_relu_kernel<<<gemmBlocks, 256>>>(bufA, W2, b2, bufB, M);

    // Final aggregation + head
    zero_kernel<<<zeroBlocks, 256>>>(bufA, n4);
    spmm_kernel<<<spmmBlocks, 256>>>(erow, ecol, eval, bufB, bufA, nE);
    head_kernel<<<headBlocks, 256>>>(bufA, Wout, bout, out, M);
}

// round 10
// speedup vs baseline: 1.9270x; 1.8999x over previous
#include <cuda_runtime.h>
#include <cuda_bf16.h>
#include <math.h>

#define N_MAX 100000
#define E_MAX 1600000
#define D 128

// Scratch (static __device__ per allocation rules)
__device__ float g_bufA[(size_t)N_MAX * D];
__device__ float g_bufB[(size_t)N_MAX * D];
__device__ int   g_cnt[N_MAX];          // per-row counts / exclusive partials
__device__ int   g_rowptr[N_MAX + 1];
__device__ int   g_cursor[N_MAX];
__device__ int   g_scol[E_MAX];
__device__ float g_sval[E_MAX];
__device__ int   g_bsum[256];           // scan block sums

// ---------------------------------------------------------------------------
// CSR build
// ---------------------------------------------------------------------------
__global__ void zero_int_kernel(int* __restrict__ p, int n) {
    int i = blockIdx.x * blockDim.x + threadIdx.x;
    int stride = gridDim.x * blockDim.x;
    for (; i < n; i += stride) p[i] = 0;
}

__global__ void hist_kernel(const int* __restrict__ erow, int* __restrict__ cnt, int nE) {
    int i = blockIdx.x * blockDim.x + threadIdx.x;
    int stride = gridDim.x * blockDim.x;
    for (; i < nE; i += stride) atomicAdd(&cnt[erow[i]], 1);
}

// Per-block inclusive scan of 1024 elems -> exclusive partials + block sums
__global__ __launch_bounds__(1024) void scan1_kernel(
    const int* __restrict__ cnt, int* __restrict__ excl, int* __restrict__ bsum, int n)
{
    __shared__ int s[1024];
    int tid = threadIdx.x;
    int i = blockIdx.x * 1024 + tid;
    int v = (i < n) ? cnt[i] : 0;
    s[tid] = v;
    __syncthreads();
    #pragma unroll
    for (int o = 1; o < 1024; o <<= 1) {
        int t = (tid >= o) ? s[tid - o] : 0;
        __syncthreads();
        s[tid] += t;
        __syncthreads();
    }
    if (i < n) excl[i] = s[tid] - v;     // exclusive within block
    if (tid == 1023) bsum[blockIdx.x] = s[1023];
}

// Exclusive scan of block sums (single block, <=256 blocks)
__global__ __launch_bounds__(256) void scan2_kernel(int* __restrict__ bsum, int nb) {
    __shared__ int s[256];
    int tid = threadIdx.x;
    int v = (tid < nb) ? bsum[tid] : 0;
    s[tid] = v;
    __syncthreads();
    #pragma unroll
    for (int o = 1; o < 256; o <<= 1) {
        int t = (tid >= o) ? s[tid - o] : 0;
        __syncthreads();
        s[tid] += t;
        __syncthreads();
    }
    if (tid < nb) bsum[tid] = s[tid] - v;  // exclusive
}

// Combine: rowptr[i] = excl[i] + bsum[block(i)]; also init cursor, rowptr[n]=nE
__global__ void scan3_kernel(
    const int* __restrict__ excl, const int* __restrict__ bsum,
    int* __restrict__ rowptr, int* __restrict__ cursor, int n, int nE)
{
    int i = blockIdx.x * blockDim.x + threadIdx.x;
    int stride = gridDim.x * blockDim.x;
    for (; i <= n; i += stride) {
        if (i < n) {
            int rp = excl[i] + bsum[i >> 10];
            rowptr[i] = rp;
            cursor[i] = rp;
        } else {
            rowptr[n] = nE;
        }
    }
}

__global__ void scatter_kernel(
    const int* __restrict__ erow, const int* __restrict__ ecol,
    const float* __restrict__ eval, int* __restrict__ cursor,
    int* __restrict__ scol, float* __restrict__ sval, int nE)
{
    int i = blockIdx.x * blockDim.x + threadIdx.x;
    int stride = gridDim.x * blockDim.x;
    for (; i < nE; i += stride) {
        int r = erow[i];
        int pos = atomicAdd(&cursor[r], 1);
        scol[pos] = ecol[i];
        sval[pos] = eval[i];
    }
}

// ---------------------------------------------------------------------------
// CSR SpMM, D=128, fused bias + ReLU: out[r] = relu(sum val*X[col] + bias)
// One warp per row; register accumulation, no atomics.
// ---------------------------------------------------------------------------
__global__ __launch_bounds__(256) void spmm_csr_bias_relu_kernel(
    const int* __restrict__ rowptr, const int* __restrict__ scol,
    const float* __restrict__ sval, const float* __restrict__ X,
    const float* __restrict__ bias, float* __restrict__ out, int M)
{
    int gt = blockIdx.x * blockDim.x + threadIdx.x;
    int r = gt >> 5;
    int lane = gt & 31;
    if (r >= M) return;

    int beg = rowptr[r];
    int end = rowptr[r + 1];

    float4 acc = make_float4(0.f, 0.f, 0.f, 0.f);
    int i = beg;
    for (; i + 4 <= end; i += 4) {
        int c0 = scol[i], c1 = scol[i + 1], c2 = scol[i + 2], c3 = scol[i + 3];
        float v0 = sval[i], v1 = sval[i + 1], v2 = sval[i + 2], v3 = sval[i + 3];
        float4 x0 = *reinterpret_cast<const float4*>(X + (size_t)c0 * D + lane * 4);
        float4 x1 = *reinterpret_cast<const float4*>(X + (size_t)c1 * D + lane * 4);
        float4 x2 = *reinterpret_cast<const float4*>(X + (size_t)c2 * D + lane * 4);
        float4 x3 = *reinterpret_cast<const float4*>(X + (size_t)c3 * D + lane * 4);
        acc.x = fmaf(v0, x0.x, acc.x); acc.y = fmaf(v0, x0.y, acc.y);
        acc.z = fmaf(v0, x0.z, acc.z); acc.w = fmaf(v0, x0.w, acc.w);
        acc.x = fmaf(v1, x1.x, acc.x); acc.y = fmaf(v1, x1.y, acc.y);
        acc.z = fmaf(v1, x1.z, acc.z); acc.w = fmaf(v1, x1.w, acc.w);
        acc.x = fmaf(v2, x2.x, acc.x); acc.y = fmaf(v2, x2.y, acc.y);
        acc.z = fmaf(v2, x2.z, acc.z); acc.w = fmaf(v2, x2.w, acc.w);
        acc.x = fmaf(v3, x3.x, acc.x); acc.y = fmaf(v3, x3.y, acc.y);
        acc.z = fmaf(v3, x3.z, acc.z); acc.w = fmaf(v3, x3.w, acc.w);
    }
    for (; i < end; i++) {
        int c = scol[i];
        float v = sval[i];
        float4 xv = *reinterpret_cast<const float4*>(X + (size_t)c * D + lane * 4);
        acc.x = fmaf(v, xv.x, acc.x); acc.y = fmaf(v, xv.y, acc.y);
        acc.z = fmaf(v, xv.z, acc.z); acc.w = fmaf(v, xv.w, acc.w);
    }

    const float4 b = *reinterpret_cast<const float4*>(bias + lane * 4);
    float4 o;
    o.x = fmaxf(acc.x + b.x, 0.f);
    o.y = fmaxf(acc.y + b.y, 0.f);
    o.z = fmaxf(acc.z + b.z, 0.f);
    o.w = fmaxf(acc.w + b.w, 0.f);
    *reinterpret_cast<float4*>(out + (size_t)r * D + lane * 4) = o;
}

// ---------------------------------------------------------------------------
// Scalar CSR SpMM + softplus: out[r] = softplus(sum val*t[col] + bout)
// ---------------------------------------------------------------------------
__global__ __launch_bounds__(256) void spmm_csr_scalar_softplus_kernel(
    const int* __restrict__ rowptr, const int* __restrict__ scol,
    const float* __restrict__ sval, const float* __restrict__ t,
    const float* __restrict__ bout, float* __restrict__ out, int M)
{
    int r = blockIdx.x * blockDim.x + threadIdx.x;
    if (r >= M) return;
    int beg = rowptr[r], end = rowptr[r + 1];
    float acc = 0.f;
    for (int i = beg; i < end; i++)
        acc = fmaf(sval[i], t[scol[i]], acc);
    float s = acc + bout[0];
    out[r] = fmaxf(s, 0.f) + log1pf(expf(-fabsf(s)));
}

// ---------------------------------------------------------------------------
// C[M,128] = A[M,128] @ W[128,128]  (no epilogue — moved into SpMM)
// ---------------------------------------------------------------------------
#define BM 64
#define BK 32
#define AS_LD (BK + 1)

__global__ __launch_bounds__(256) void gemm_plain_kernel(
    const float* __restrict__ A, const float* __restrict__ W,
    float* __restrict__ C, int M)
{
    __shared__ float As[BM * AS_LD];
    __shared__ float Ws[BK * D];

    const int tid = threadIdx.x;
    const int tx = tid & 15;
    const int ty = tid >> 4;
    const int row0 = blockIdx.x * BM;

    float acc[4][8];
    #pragma unroll
    for (int i = 0; i < 4; i++)
        #pragma unroll
        for (int j = 0; j < 8; j++) acc[i][j] = 0.f;

    for (int k0 = 0; k0 < D; k0 += BK) {
        #pragma unroll
        for (int i = 0; i < 2; i++) {
            int fid = tid + i * 256;
            int m   = fid >> 3;
            int kk  = (fid & 7) << 2;
            int gr  = row0 + m;
            float4 v = make_float4(0.f, 0.f, 0.f, 0.f);
            if (gr < M)
                v = *reinterpret_cast<const float4*>(A + (size_t)gr * D + k0 + kk);
            float* s = As + m * AS_LD + kk;
            s[0] = v.x; s[1] = v.y; s[2] = v.z; s[3] = v.w;
        }
        #pragma unroll
        for (int i = 0; i < 4; i++) {
            int fid = tid + i * 256;
            int k   = fid >> 5;
            int n4  = (fid & 31) << 2;
            *reinterpret_cast<float4*>(Ws + k * D + n4) =
                *reinterpret_cast<const float4*>(W + (size_t)(k0 + k) * D + n4);
        }
        __syncthreads();

        #pragma unroll
        for (int kk = 0; kk < BK; kk++) {
            float a[4];
            #pragma unroll
            for (int i = 0; i < 4; i++)
                a[i] = As[(ty * 4 + i) * AS_LD + kk];
            const float4 w0 = *reinterpret_cast<const float4*>(Ws + kk * D + tx * 8);
            const float4 w1 = *reinterpret_cast<const float4*>(Ws + kk * D + tx * 8 + 4);
            #pragma unroll
            for (int i = 0; i < 4; i++) {
                acc[i][0] += a[i] * w0.x;
                acc[i][1] += a[i] * w0.y;
                acc[i][2] += a[i] * w0.z;
                acc[i][3] += a[i] * w0.w;
                acc[i][4] += a[i] * w1.x;
                acc[i][5] += a[i] * w1.y;
                acc[i][6] += a[i] * w1.z;
                acc[i][7] += a[i] * w1.w;
            }
        }
        __syncthreads();
    }

    #pragma unroll
    for (int i = 0; i < 4; i++) {
        int gr = row0 + ty * 4 + i;
        if (gr >= M) continue;
        float4 o0 = make_float4(acc[i][0], acc[i][1], acc[i][2], acc[i][3]);
        float4 o1 = make_float4(acc[i][4], acc[i][5], acc[i][6], acc[i][7]);
        *reinterpret_cast<float4*>(C + (size_t)gr * D + tx * 8)     = o0;
        *reinterpret_cast<float4*>(C + (size_t)gr * D + tx * 8 + 4) = o1;
    }
}

// ---------------------------------------------------------------------------
// t[r] = dot(H[r], Wout)  — one warp per row (head GEMV, no activation)
// ---------------------------------------------------------------------------
__global__ __launch_bounds__(256) void gemv_kernel(
    const float* __restrict__ H, const float* __restrict__ Wout,
    float* __restrict__ t, int M)
{
    int gtid = blockIdx.x * blockDim.x + threadIdx.x;
    int r = gtid >> 5;
    int lane = gtid & 31;
    if (r >= M) return;

    const float4 h = *reinterpret_cast<const float4*>(H + (size_t)r * D + lane * 4);
    const float4 w = *reinterpret_cast<const float4*>(Wout + lane * 4);
    float s = h.x * w.x + h.y * w.y + h.z * w.z + h.w * w.w;
    #pragma unroll
    for (int o = 16; o > 0; o >>= 1)
        s += __shfl_xor_sync(0xFFFFFFFFu, s, o);
    if (lane == 0) t[r] = s;
}

// ---------------------------------------------------------------------------
// Launch
// ---------------------------------------------------------------------------
extern "C" void kernel_launch(void* const* d_in, const int* in_sizes, int n_in,
                              void* d_out, int out_size)
{
    const float* x     = (const float*)d_in[0];
    const int*   erow  = (const int*)  d_in[1];
    const int*   ecol  = (const int*)  d_in[2];
    const float* eval  = (const float*)d_in[3];
    const float* W1    = (const float*)d_in[4];
    const float* b1    = (const float*)d_in[5];
    const float* W2    = (const float*)d_in[6];
    const float* b2    = (const float*)d_in[7];
    const float* Wout  = (const float*)d_in[8];
    const float* bout  = (const float*)d_in[9];
    float* out = (float*)d_out;

    const int M  = in_sizes[0] / D;     // 100000
    const int nE = in_sizes[1];         // 1600000

    float *bufA, *bufB, *sval;
    int *cnt, *rowptr, *cursor, *scol, *bsum;
    cudaGetSymbolAddress((void**)&bufA,   g_bufA);
    cudaGetSymbolAddress((void**)&bufB,   g_bufB);
    cudaGetSymbolAddress((void**)&cnt,    g_cnt);
    cudaGetSymbolAddress((void**)&rowptr, g_rowptr);
    cudaGetSymbolAddress((void**)&cursor, g_cursor);
    cudaGetSymbolAddress((void**)&scol,   g_scol);
    cudaGetSymbolAddress((void**)&sval,   g_sval);
    cudaGetSymbolAddress((void**)&bsum,   g_bsum);

    const int nb = (M + 1023) / 1024;                   // scan blocks (98)
    const int spmmBlocks = (M * 32 + 255) / 256;        // 1 warp/row
    const int gemmBlocks = (M + BM - 1) / BM;
    const int rowBlocks  = (M + 255) / 256;

    // --- CSR build (every replay; deterministic work) ---
    zero_int_kernel<<<128, 256>>>(cnt, M);
    hist_kernel<<<1024, 256>>>(erow, cnt, nE);
    scan1_kernel<<<nb, 1024>>>(cnt, cnt, bsum, M);      // in-place exclusive partials
    scan2_kernel<<<1, 256>>>(bsum, nb);
    scan3_kernel<<<256, 256>>>(cnt, bsum, rowptr, cursor, M, nE);
    scatter_kernel<<<1024, 256>>>(erow, ecol, eval, cursor, scol, sval, nE);

    // --- Layer 1: h1 = relu(A @ (x @ W1) + b1) ---
    gemm_plain_kernel<<<gemmBlocks, 256>>>(x, W1, bufB, M);
    spmm_csr_bias_relu_kernel<<<spmmBlocks, 256>>>(rowptr, scol, sval, bufB, b1, bufA, M);

    // --- Layer 2: h2 = relu(A @ (h1 @ W2) + b2) ---
    gemm_plain_kernel<<<gemmBlocks, 256>>>(bufA, W2, bufB, M);
    spmm_csr_bias_relu_kernel<<<spmmBlocks, 256>>>(rowptr, scol, sval, bufB, b2, bufA, M);

    // --- Head: out = softplus(A @ (h2 @ Wout) + bout) ---
    gemv_kernel<<<spmmBlocks, 256>>>(bufA, Wout, bufB, M);   // bufB[0..M) = t
    spmm_csr_scalar_softplus_kernel<<<rowBlocks, 256>>>(rowptr, scol, sval, bufB, bout, out, M);
}

// round 12
// speedup vs baseline: 2.4559x; 1.2744x over previous
#include <cuda_runtime.h>
#include <cuda_bf16.h>
#include <math.h>
#include <stdint.h>

#define N_MAX 100000
#define E_MAX 1600000
#define D 128
#define WP 136                      // padded pitch (bf16 elems) for mma tiles

// Scratch (static __device__ per allocation rules)
__device__ float g_bufA[(size_t)N_MAX * D];
__device__ float g_bufB[(size_t)N_MAX * D];
__device__ int   g_cnt[N_MAX];
__device__ int   g_rowptr[N_MAX + 1];
__device__ int   g_cursor[N_MAX];
__device__ int   g_scol[E_MAX];
__device__ float g_sval[E_MAX];
__device__ int   g_bsum[256];
// Pre-split weights, transposed Bt[n][k], padded pitch WP (bf16 hi/lo)
__device__ unsigned short g_w_hi[2][128 * WP];
__device__ unsigned short g_w_lo[2][128 * WP];

// ===========================================================================
// Weight prep: W[k][n] fp32 -> Bt[n][k] bf16 hi/lo, padded pitch WP
// ===========================================================================
__global__ void prep_w_kernel(const float* __restrict__ W1,
                              const float* __restrict__ W2) {
    const float* W = (blockIdx.x == 0) ? W1 : W2;
    unsigned short* hi = g_w_hi[blockIdx.x];
    unsigned short* lo = g_w_lo[blockIdx.x];
    for (int idx = threadIdx.x; idx < 128 * 128; idx += blockDim.x) {
        int k = idx >> 7, n = idx & 127;
        float w = W[idx];                               // W[k][n]
        __nv_bfloat16 h = __float2bfloat16_rn(w);
        float wl = w - __bfloat162float(h);
        hi[n * WP + k] = __bfloat16_as_ushort(h);
        lo[n * WP + k] = __bfloat16_as_ushort(__float2bfloat16_rn(wl));
    }
}

// ===========================================================================
// GEMM: C[M,128] = A[M,128] @ W  via split-bf16 mma.sync (HMMA, bf16x3)
// CTA: 128 rows x 128 cols, 256 threads. Warp grid 4x2 -> 32x64 per warp.
// ===========================================================================
#define SA_HI 0
#define SA_LO (128 * WP * 2)
#define SB_HI (2 * 128 * WP * 2)
#define SB_LO (3 * 128 * WP * 2)
#define SM_GEMM (4 * 128 * WP * 2)     // 139264 B

#define MMA_BF16(c, a, b) \
    asm volatile( \
        "mma.sync.aligned.m16n8k16.row.col.f32.bf16.bf16.f32 " \
        "{%0,%1,%2,%3}, {%4,%5,%6,%7}, {%8,%9}, {%0,%1,%2,%3};" \
        : "+f"((c)[0]), "+f"((c)[1]), "+f"((c)[2]), "+f"((c)[3]) \
        : "r"((a)[0]), "r"((a)[1]), "r"((a)[2]), "r"((a)[3]), \
          "r"((b)[0]), "r"((b)[1]))

__global__ __launch_bounds__(256) void gemm_mma_kernel(
    const float* __restrict__ A, int widx, float* __restrict__ C, int M)
{
    extern __shared__ char smem[];
    const int tid = threadIdx.x;
    const int wid = tid >> 5, lane = tid & 31;
    const int row0 = blockIdx.x * 128;

    // Stage W tiles (linear copy of padded images)
    {
        const uint4* whi = reinterpret_cast<const uint4*>(g_w_hi[widx]);
        const uint4* wlo = reinterpret_cast<const uint4*>(g_w_lo[widx]);
        uint4* dh = reinterpret_cast<uint4*>(smem + SB_HI);
        uint4* dl = reinterpret_cast<uint4*>(smem + SB_LO);
        for (int i = tid; i < (128 * WP * 2) / 16; i += 256) {
            dh[i] = whi[i];
            dl[i] = wlo[i];
        }
    }
    // Stage A: fp32 -> bf16 hi/lo
    {
        unsigned short* sAhi = reinterpret_cast<unsigned short*>(smem + SA_HI);
        unsigned short* sAlo = reinterpret_cast<unsigned short*>(smem + SA_LO);
        for (int idx = tid; idx < 128 * 64; idx += 256) {
            int row = idx >> 6;
            int cp  = (idx & 63) << 1;
            int gr  = row0 + row;
            float2 a = make_float2(0.f, 0.f);
            if (gr < M)
                a = *reinterpret_cast<const float2*>(A + (size_t)gr * D + cp);
            __nv_bfloat16 h0 = __float2bfloat16_rn(a.x);
            __nv_bfloat16 h1 = __float2bfloat16_rn(a.y);
            __nv_bfloat16 l0 = __float2bfloat16_rn(a.x - __bfloat162float(h0));
            __nv_bfloat16 l1 = __float2bfloat16_rn(a.y - __bfloat162float(h1));
            int o = row * WP + cp;
            *reinterpret_cast<uint32_t*>(sAhi + o) =
                (uint32_t)__bfloat16_as_ushort(h0) |
                ((uint32_t)__bfloat16_as_ushort(h1) << 16);
            *reinterpret_cast<uint32_t*>(sAlo + o) =
                (uint32_t)__bfloat16_as_ushort(l0) |
                ((uint32_t)__bfloat16_as_ushort(l1) << 16);
        }
    }
    __syncthreads();

    const int wm = (wid & 3) * 32;       // warp row base
    const int wn = (wid >> 2) * 64;      // warp col base
    const int qr = lane >> 2;            // 0..7
    const int qc = (lane & 3) * 2;       // 0,2,4,6

    const uint32_t* pAh = reinterpret_cast<const uint32_t*>(smem + SA_HI);
    const uint32_t* pAl = reinterpret_cast<const uint32_t*>(smem + SA_LO);
    const uint32_t* pBh = reinterpret_cast<const uint32_t*>(smem + SB_HI);
    const uint32_t* pBl = reinterpret_cast<const uint32_t*>(smem + SB_LO);
    const int WPW = WP / 2;              // 68 words per row

    float acc[2][8][4];
    #pragma unroll
    for (int mt = 0; mt < 2; mt++)
        #pragma unroll
        for (int nt = 0; nt < 8; nt++)
            #pragma unroll
            for (int j = 0; j < 4; j++) acc[mt][nt][j] = 0.f;

    #pragma unroll
    for (int ks = 0; ks < 8; ks++) {
        const int kw = (ks * 16 + qc) >> 1;   // word offset of this lane's k pair
        uint32_t ah[2][4], al[2][4];
        #pragma unroll
        for (int mt = 0; mt < 2; mt++) {
            int r = wm + mt * 16 + qr;
            int w0 = r * WPW + kw;
            int w1 = (r + 8) * WPW + kw;
            ah[mt][0] = pAh[w0];     ah[mt][1] = pAh[w1];
            ah[mt][2] = pAh[w0 + 4]; ah[mt][3] = pAh[w1 + 4];
            al[mt][0] = pAl[w0];     al[mt][1] = pAl[w1];
            al[mt][2] = pAl[w0 + 4]; al[mt][3] = pAl[w1 + 4];
        }
        uint32_t bh[8][2], bl[8][2];
        #pragma unroll
        for (int nt = 0; nt < 8; nt++) {
            int n = wn + nt * 8 + qr;
            int w0 = n * WPW + kw;
            bh[nt][0] = pBh[w0]; bh[nt][1] = pBh[w0 + 4];
            bl[nt][0] = pBl[w0]; bl[nt][1] = pBl[w0 + 4];
        }
        #pragma unroll
        for (int mt = 0; mt < 2; mt++)
            #pragma unroll
            for (int nt = 0; nt < 8; nt++) {
                MMA_BF16(acc[mt][nt], ah[mt], bh[nt]);
                MMA_BF16(acc[mt][nt], ah[mt], bl[nt]);
                MMA_BF16(acc[mt][nt], al[mt], bh[nt]);
            }
    }

    // Epilogue: direct global stores (C fragment: c0c1 @ (r,qc), c2c3 @ (r+8,qc))
    #pragma unroll
    for (int mt = 0; mt < 2; mt++) {
        int r = row0 + wm + mt * 16 + qr;
        #pragma unroll
        for (int nt = 0; nt < 8; nt++) {
            int col = wn + nt * 8 + qc;
            if (r < M)
                *reinterpret_cast<float2*>(C + (size_t)r * D + col) =
                    make_float2(acc[mt][nt][0], acc[mt][nt][1]);
            if (r + 8 < M)
                *reinterpret_cast<float2*>(C + (size_t)(r + 8) * D + col) =
                    make_float2(acc[mt][nt][2], acc[mt][nt][3]);
        }
    }
}

// ===========================================================================
// CSR build
// ===========================================================================
__global__ void zero_int_kernel(int* __restrict__ p, int n) {
    int i = blockIdx.x * blockDim.x + threadIdx.x;
    int stride = gridDim.x * blockDim.x;
    for (; i < n; i += stride) p[i] = 0;
}

__global__ void hist_kernel(const int* __restrict__ erow, int* __restrict__ cnt, int nE) {
    int i = blockIdx.x * blockDim.x + threadIdx.x;
    int stride = gridDim.x * blockDim.x;
    for (; i < nE; i += stride) atomicAdd(&cnt[erow[i]], 1);
}

__global__ __launch_bounds__(1024) void scan1_kernel(
    const int* __restrict__ cnt, int* __restrict__ excl, int* __restrict__ bsum, int n)
{
    __shared__ int s[1024];
    int tid = threadIdx.x;
    int i = blockIdx.x * 1024 + tid;
    int v = (i < n) ? cnt[i] : 0;
    s[tid] = v;
    __syncthreads();
    #pragma unroll
    for (int o = 1; o < 1024; o <<= 1) {
        int t = (tid >= o) ? s[tid - o] : 0;
        __syncthreads();
        s[tid] += t;
        __syncthreads();
    }
    if (i < n) excl[i] = s[tid] - v;
    if (tid == 1023) bsum[blockIdx.x] = s[1023];
}

__global__ __launch_bounds__(256) void scan2_kernel(int* __restrict__ bsum, int nb) {
    __shared__ int s[256];
    int tid = threadIdx.x;
    int v = (tid < nb) ? bsum[tid] : 0;
    s[tid] = v;
    __syncthreads();
    #pragma unroll
    for (int o = 1; o < 256; o <<= 1) {
        int t = (tid >= o) ? s[tid - o] : 0;
        __syncthreads();
        s[tid] += t;
        __syncthreads();
    }
    if (tid < nb) bsum[tid] = s[tid] - v;
}

__global__ void scan3_kernel(
    const int* __restrict__ excl, const int* __restrict__ bsum,
    int* __restrict__ rowptr, int* __restrict__ cursor, int n, int nE)
{
    int i = blockIdx.x * blockDim.x + threadIdx.x;
    int stride = gridDim.x * blockDim.x;
    for (; i <= n; i += stride) {
        if (i < n) {
            int rp = excl[i] + bsum[i >> 10];
            rowptr[i] = rp;
            cursor[i] = rp;
        } else {
            rowptr[n] = nE;
        }
    }
}

__global__ void scatter_kernel(
    const int* __restrict__ erow, const int* __restrict__ ecol,
    const float* __restrict__ eval, int* __restrict__ cursor,
    int* __restrict__ scol, float* __restrict__ sval, int nE)
{
    int i = blockIdx.x * blockDim.x + threadIdx.x;
    int stride = gridDim.x * blockDim.x;
    for (; i < nE; i += stride) {
        int r = erow[i];
        int pos = atomicAdd(&cursor[r], 1);
        scol[pos] = ecol[i];
        sval[pos] = eval[i];
    }
}

// ===========================================================================
// CSR SpMM, D=128, fused bias + ReLU (one warp per row)
// ===========================================================================
__global__ __launch_bounds__(256) void spmm_csr_bias_relu_kernel(
    const int* __restrict__ rowptr, const int* __restrict__ scol,
    const float* __restrict__ sval, const float* __restrict__ X,
    const float* __restrict__ bias, float* __restrict__ out, int M)
{
    int gt = blockIdx.x * blockDim.x + threadIdx.x;
    int r = gt >> 5;
    int lane = gt & 31;
    if (r >= M) return;

    int beg = rowptr[r];
    int end = rowptr[r + 1];

    float4 acc = make_float4(0.f, 0.f, 0.f, 0.f);
    int i = beg;
    for (; i + 4 <= end; i += 4) {
        int c0 = scol[i], c1 = scol[i + 1], c2 = scol[i + 2], c3 = scol[i + 3];
        float v0 = sval[i], v1 = sval[i + 1], v2 = sval[i + 2], v3 = sval[i + 3];
        float4 x0 = *reinterpret_cast<const float4*>(X + (size_t)c0 * D + lane * 4);
        float4 x1 = *reinterpret_cast<const float4*>(X + (size_t)c1 * D + lane * 4);
        float4 x2 = *reinterpret_cast<const float4*>(X + (size_t)c2 * D + lane * 4);
        float4 x3 = *reinterpret_cast<const float4*>(X + (size_t)c3 * D + lane * 4);
        acc.x = fmaf(v0, x0.x, acc.x); acc.y = fmaf(v0, x0.y, acc.y);
        acc.z = fmaf(v0, x0.z, acc.z); acc.w = fmaf(v0, x0.w, acc.w);
        acc.x = fmaf(v1, x1.x, acc.x); acc.y = fmaf(v1, x1.y, acc.y);
        acc.z = fmaf(v1, x1.z, acc.z); acc.w = fmaf(v1, x1.w, acc.w);
        acc.x = fmaf(v2, x2.x, acc.x); acc.y = fmaf(v2, x2.y, acc.y);
        acc.z = fmaf(v2, x2.z, acc.z); acc.w = fmaf(v2, x2.w, acc.w);
        acc.x = fmaf(v3, x3.x, acc.x); acc.y = fmaf(v3, x3.y, acc.y);
        acc.z = fmaf(v3, x3.z, acc.z); acc.w = fmaf(v3, x3.w, acc.w);
    }
    for (; i < end; i++) {
        int c = scol[i];
        float v = sval[i];
        float4 xv = *reinterpret_cast<const float4*>(X + (size_t)c * D + lane * 4);
        acc.x = fmaf(v, xv.x, acc.x); acc.y = fmaf(v, xv.y, acc.y);
        acc.z = fmaf(v, xv.z, acc.z); acc.w = fmaf(v, xv.w, acc.w);
    }

    const float4 b = *reinterpret_cast<const float4*>(bias + lane * 4);
    float4 o;
    o.x = fmaxf(acc.x + b.x, 0.f);
    o.y = fmaxf(acc.y + b.y, 0.f);
    o.z = fmaxf(acc.z + b.z, 0.f);
    o.w = fmaxf(acc.w + b.w, 0.f);
    *reinterpret_cast<float4*>(out + (size_t)r * D + lane * 4) = o;
}

// ---------------------------------------------------------------------------
// Scalar CSR SpMM + softplus
// ---------------------------------------------------------------------------
__global__ __launch_bounds__(256) void spmm_csr_scalar_softplus_kernel(
    const int* __restrict__ rowptr, const int* __restrict__ scol,
    const float* __restrict__ sval, const float* __restrict__ t,
    const float* __restrict__ bout, float* __restrict__ out, int M)
{
    int r = blockIdx.x * blockDim.x + threadIdx.x;
    if (r >= M) return;
    int beg = rowptr[r], end = rowptr[r + 1];
    float acc = 0.f;
    for (int i = beg; i < end; i++)
        acc = fmaf(sval[i], t[scol[i]], acc);
    float s = acc + bout[0];
    out[r] = fmaxf(s, 0.f) + log1pf(expf(-fabsf(s)));
}

// ---------------------------------------------------------------------------
// t[r] = dot(H[r], Wout) — one warp per row
// ---------------------------------------------------------------------------
__global__ __launch_bounds__(256) void gemv_kernel(
    const float* __restrict__ H, const float* __restrict__ Wout,
    float* __restrict__ t, int M)
{
    int gtid = blockIdx.x * blockDim.x + threadIdx.x;
    int r = gtid >> 5;
    int lane = gtid & 31;
    if (r >= M) return;

    const float4 h = *reinterpret_cast<const float4*>(H + (size_t)r * D + lane * 4);
    const float4 w = *reinterpret_cast<const float4*>(Wout + lane * 4);
    float s = h.x * w.x + h.y * w.y + h.z * w.z + h.w * w.w;
    #pragma unroll
    for (int o = 16; o > 0; o >>= 1)
        s += __shfl_xor_sync(0xFFFFFFFFu, s, o);
    if (lane == 0) t[r] = s;
}

// ===========================================================================
// Launch
// ===========================================================================
extern "C" void kernel_launch(void* const* d_in, const int* in_sizes, int n_in,
                              void* d_out, int out_size)
{
    const float* x     = (const float*)d_in[0];
    const int*   erow  = (const int*)  d_in[1];
    const int*   ecol  = (const int*)  d_in[2];
    const float* eval  = (const float*)d_in[3];
    const float* W1    = (const float*)d_in[4];
    const float* b1    = (const float*)d_in[5];
    const float* W2    = (const float*)d_in[6];
    const float* b2    = (const float*)d_in[7];
    const float* Wout  = (const float*)d_in[8];
    const float* bout  = (const float*)d_in[9];
    float* out = (float*)d_out;

    const int M  = in_sizes[0] / D;     // 100000
    const int nE = in_sizes[1];         // 1600000

    float *bufA, *bufB, *sval;
    int *cnt, *rowptr, *cursor, *scol, *bsum;
    cudaGetSymbolAddress((void**)&bufA,   g_bufA);
    cudaGetSymbolAddress((void**)&bufB,   g_bufB);
    cudaGetSymbolAddress((void**)&cnt,    g_cnt);
    cudaGetSymbolAddress((void**)&rowptr, g_rowptr);
    cudaGetSymbolAddress((void**)&cursor, g_cursor);
    cudaGetSymbolAddress((void**)&scol,   g_scol);
    cudaGetSymbolAddress((void**)&sval,   g_sval);
    cudaGetSymbolAddress((void**)&bsum,   g_bsum);

    cudaFuncSetAttribute(gemm_mma_kernel,
                         cudaFuncAttributeMaxDynamicSharedMemorySize, SM_GEMM);

    const int nb = (M + 1023) / 1024;
    const int spmmBlocks = (M * 32 + 255) / 256;
    const int tileBlocks = (M + 127) / 128;
    const int rowBlocks  = (M + 255) / 256;

    // Weight prep (independent of CSR build)
    prep_w_kernel<<<2, 256>>>(W1, W2);

    // CSR build
    zero_int_kernel<<<128, 256>>>(cnt, M);
    hist_kernel<<<1024, 256>>>(erow, cnt, nE);
    scan1_kernel<<<nb, 1024>>>(cnt, cnt, bsum, M);
    scan2_kernel<<<1, 256>>>(bsum, nb);
    scan3_kernel<<<256, 256>>>(cnt, bsum, rowptr, cursor, M, nE);
    scatter_kernel<<<1024, 256>>>(erow, ecol, eval, cursor, scol, sval, nE);

    // Layer 1: h1 = relu(A @ (x @ W1) + b1)
    gemm_mma_kernel<<<tileBlocks, 256, SM_GEMM>>>(x, 0, bufB, M);
    spmm_csr_bias_relu_kernel<<<spmmBlocks, 256>>>(rowptr, scol, sval, bufB, b1, bufA, M);

    // Layer 2: h2 = relu(A @ (h1 @ W2) + b2)
    gemm_mma_kernel<<<tileBlocks, 256, SM_GEMM>>>(bufA, 1, bufB, M);
    spmm_csr_bias_relu_kernel<<<spmmBlocks, 256>>>(rowptr, scol, sval, bufB, b2, bufA, M);

    // Head: out = softplus(A @ (h2 @ Wout) + bout)
    gemv_kernel<<<spmmBlocks, 256>>>(bufA, Wout, bufB, M);
    spmm_csr_scalar_softplus_kernel<<<rowBlocks, 256>>>(rowptr, scol, sval, bufB, bout, out, M);
}

// round 13
// speedup vs baseline: 2.6657x; 1.0855x over previous
#include <cuda_runtime.h>
#include <cuda_bf16.h>
#include <cuda_fp16.h>
#include <math.h>
#include <stdint.h>

#define N_MAX 100000
#define E_MAX 1600000
#define D 128
#define WP 136                      // padded pitch (bf16 elems) for mma tiles

// Scratch (static __device__ per allocation rules)
__device__ float g_bufA[(size_t)N_MAX * D];          // fp32 hidden state
__device__ __half g_bufH[(size_t)N_MAX * D];         // fp16 GEMM output (XW)
__device__ float g_t[N_MAX];                         // head GEMV output
__device__ int   g_cnt[N_MAX];
__device__ int   g_rowptr[N_MAX + 1];
__device__ int   g_cursor[N_MAX];
__device__ int   g_scol[E_MAX];
__device__ float g_sval[E_MAX];
__device__ int   g_bsum[256];
// Pre-split weights, transposed Bt[n][k], padded pitch WP (bf16 hi/lo)
__device__ unsigned short g_w_hi[2][128 * WP];
__device__ unsigned short g_w_lo[2][128 * WP];

// ===========================================================================
// Weight prep: W[k][n] fp32 -> Bt[n][k] bf16 hi/lo, padded pitch WP
// ===========================================================================
__global__ void prep_w_kernel(const float* __restrict__ W1,
                              const float* __restrict__ W2) {
    const float* W = (blockIdx.x == 0) ? W1 : W2;
    unsigned short* hi = g_w_hi[blockIdx.x];
    unsigned short* lo = g_w_lo[blockIdx.x];
    for (int idx = threadIdx.x; idx < 128 * 128; idx += blockDim.x) {
        int k = idx >> 7, n = idx & 127;
        float w = W[idx];                               // W[k][n]
        __nv_bfloat16 h = __float2bfloat16_rn(w);
        float wl = w - __bfloat162float(h);
        hi[n * WP + k] = __bfloat16_as_ushort(h);
        lo[n * WP + k] = __bfloat16_as_ushort(__float2bfloat16_rn(wl));
    }
}

// ===========================================================================
// GEMM: C16[M,128] = fp16( A[M,128] @ W )  via split-bf16 mma.sync (bf16x3)
// CTA: 128 rows x 128 cols, 256 threads. Warp grid 4x2 -> 32x64 per warp.
// ===========================================================================
#define SA_HI 0
#define SA_LO (128 * WP * 2)
#define SB_HI (2 * 128 * WP * 2)
#define SB_LO (3 * 128 * WP * 2)
#define SM_GEMM (4 * 128 * WP * 2)     // 139264 B

#define MMA_BF16(c, a, b) \
    asm volatile( \
        "mma.sync.aligned.m16n8k16.row.col.f32.bf16.bf16.f32 " \
        "{%0,%1,%2,%3}, {%4,%5,%6,%7}, {%8,%9}, {%0,%1,%2,%3};" \
        : "+f"((c)[0]), "+f"((c)[1]), "+f"((c)[2]), "+f"((c)[3]) \
        : "r"((a)[0]), "r"((a)[1]), "r"((a)[2]), "r"((a)[3]), \
          "r"((b)[0]), "r"((b)[1]))

__global__ __launch_bounds__(256) void gemm_mma_kernel(
    const float* __restrict__ A, int widx, __half* __restrict__ C16, int M)
{
    extern __shared__ char smem[];
    const int tid = threadIdx.x;
    const int wid = tid >> 5, lane = tid & 31;
    const int row0 = blockIdx.x * 128;

    // Stage W tiles (linear copy of padded images)
    {
        const uint4* whi = reinterpret_cast<const uint4*>(g_w_hi[widx]);
        const uint4* wlo = reinterpret_cast<const uint4*>(g_w_lo[widx]);
        uint4* dh = reinterpret_cast<uint4*>(smem + SB_HI);
        uint4* dl = reinterpret_cast<uint4*>(smem + SB_LO);
        for (int i = tid; i < (128 * WP * 2) / 16; i += 256) {
            dh[i] = whi[i];
            dl[i] = wlo[i];
        }
    }
    // Stage A: fp32 -> bf16 hi/lo
    {
        unsigned short* sAhi = reinterpret_cast<unsigned short*>(smem + SA_HI);
        unsigned short* sAlo = reinterpret_cast<unsigned short*>(smem + SA_LO);
        for (int idx = tid; idx < 128 * 64; idx += 256) {
            int row = idx >> 6;
            int cp  = (idx & 63) << 1;
            int gr  = row0 + row;
            float2 a = make_float2(0.f, 0.f);
            if (gr < M)
                a = *reinterpret_cast<const float2*>(A + (size_t)gr * D + cp);
            __nv_bfloat16 h0 = __float2bfloat16_rn(a.x);
            __nv_bfloat16 h1 = __float2bfloat16_rn(a.y);
            __nv_bfloat16 l0 = __float2bfloat16_rn(a.x - __bfloat162float(h0));
            __nv_bfloat16 l1 = __float2bfloat16_rn(a.y - __bfloat162float(h1));
            int o = row * WP + cp;
            *reinterpret_cast<uint32_t*>(sAhi + o) =
                (uint32_t)__bfloat16_as_ushort(h0) |
                ((uint32_t)__bfloat16_as_ushort(h1) << 16);
            *reinterpret_cast<uint32_t*>(sAlo + o) =
                (uint32_t)__bfloat16_as_ushort(l0) |
                ((uint32_t)__bfloat16_as_ushort(l1) << 16);
        }
    }
    __syncthreads();

    const int wm = (wid & 3) * 32;       // warp row base
    const int wn = (wid >> 2) * 64;      // warp col base
    const int qr = lane >> 2;            // 0..7
    const int qc = (lane & 3) * 2;       // 0,2,4,6

    const uint32_t* pAh = reinterpret_cast<const uint32_t*>(smem + SA_HI);
    const uint32_t* pAl = reinterpret_cast<const uint32_t*>(smem + SA_LO);
    const uint32_t* pBh = reinterpret_cast<const uint32_t*>(smem + SB_HI);
    const uint32_t* pBl = reinterpret_cast<const uint32_t*>(smem + SB_LO);
    const int WPW = WP / 2;              // 68 words per row

    float acc[2][8][4];
    #pragma unroll
    for (int mt = 0; mt < 2; mt++)
        #pragma unroll
        for (int nt = 0; nt < 8; nt++)
            #pragma unroll
            for (int j = 0; j < 4; j++) acc[mt][nt][j] = 0.f;

    #pragma unroll
    for (int ks = 0; ks < 8; ks++) {
        const int kw = (ks * 16 + qc) >> 1;
        uint32_t ah[2][4], al[2][4];
        #pragma unroll
        for (int mt = 0; mt < 2; mt++) {
            int r = wm + mt * 16 + qr;
            int w0 = r * WPW + kw;
            int w1 = (r + 8) * WPW + kw;
            ah[mt][0] = pAh[w0];     ah[mt][1] = pAh[w1];
            ah[mt][2] = pAh[w0 + 4]; ah[mt][3] = pAh[w1 + 4];
            al[mt][0] = pAl[w0];     al[mt][1] = pAl[w1];
            al[mt][2] = pAl[w0 + 4]; al[mt][3] = pAl[w1 + 4];
        }
        uint32_t bh[8][2], bl[8][2];
        #pragma unroll
        for (int nt = 0; nt < 8; nt++) {
            int n = wn + nt * 8 + qr;
            int w0 = n * WPW + kw;
            bh[nt][0] = pBh[w0]; bh[nt][1] = pBh[w0 + 4];
            bl[nt][0] = pBl[w0]; bl[nt][1] = pBl[w0 + 4];
        }
        #pragma unroll
        for (int mt = 0; mt < 2; mt++)
            #pragma unroll
            for (int nt = 0; nt < 8; nt++) {
                MMA_BF16(acc[mt][nt], ah[mt], bh[nt]);
                MMA_BF16(acc[mt][nt], ah[mt], bl[nt]);
                MMA_BF16(acc[mt][nt], al[mt], bh[nt]);
            }
    }

    // Epilogue: fp16 stores (halves write traffic; feeds fp16 SpMM gathers)
    #pragma unroll
    for (int mt = 0; mt < 2; mt++) {
        int r = row0 + wm + mt * 16 + qr;
        #pragma unroll
        for (int nt = 0; nt < 8; nt++) {
            int col = wn + nt * 8 + qc;
            if (r < M)
                *reinterpret_cast<__half2*>(C16 + (size_t)r * D + col) =
                    __floats2half2_rn(acc[mt][nt][0], acc[mt][nt][1]);
            if (r + 8 < M)
                *reinterpret_cast<__half2*>(C16 + (size_t)(r + 8) * D + col) =
                    __floats2half2_rn(acc[mt][nt][2], acc[mt][nt][3]);
        }
    }
}

// ===========================================================================
// CSR build
// ===========================================================================
__global__ void zero_int_kernel(int* __restrict__ p, int n) {
    int i = blockIdx.x * blockDim.x + threadIdx.x;
    int stride = gridDim.x * blockDim.x;
    for (; i < n; i += stride) p[i] = 0;
}

__global__ void hist_kernel(const int* __restrict__ erow, int* __restrict__ cnt, int nE) {
    int i = blockIdx.x * blockDim.x + threadIdx.x;
    int stride = gridDim.x * blockDim.x;
    for (; i < nE; i += stride) atomicAdd(&cnt[erow[i]], 1);
}

__global__ __launch_bounds__(1024) void scan1_kernel(
    const int* __restrict__ cnt, int* __restrict__ excl, int* __restrict__ bsum, int n)
{
    __shared__ int s[1024];
    int tid = threadIdx.x;
    int i = blockIdx.x * 1024 + tid;
    int v = (i < n) ? cnt[i] : 0;
    s[tid] = v;
    __syncthreads();
    #pragma unroll
    for (int o = 1; o < 1024; o <<= 1) {
        int t = (tid >= o) ? s[tid - o] : 0;
        __syncthreads();
        s[tid] += t;
        __syncthreads();
    }
    if (i < n) excl[i] = s[tid] - v;
    if (tid == 1023) bsum[blockIdx.x] = s[1023];
}

__global__ __launch_bounds__(256) void scan2_kernel(int* __restrict__ bsum, int nb) {
    __shared__ int s[256];
    int tid = threadIdx.x;
    int v = (tid < nb) ? bsum[tid] : 0;
    s[tid] = v;
    __syncthreads();
    #pragma unroll
    for (int o = 1; o < 256; o <<= 1) {
        int t = (tid >= o) ? s[tid - o] : 0;
        __syncthreads();
        s[tid] += t;
        __syncthreads();
    }
    if (tid < nb) bsum[tid] = s[tid] - v;
}

__global__ void scan3_kernel(
    const int* __restrict__ excl, const int* __restrict__ bsum,
    int* __restrict__ rowptr, int* __restrict__ cursor, int n, int nE)
{
    int i = blockIdx.x * blockDim.x + threadIdx.x;
    int stride = gridDim.x * blockDim.x;
    for (; i <= n; i += stride) {
        if (i < n) {
            int rp = excl[i] + bsum[i >> 10];
            rowptr[i] = rp;
            cursor[i] = rp;
        } else {
            rowptr[n] = nE;
        }
    }
}

__global__ void scatter_kernel(
    const int* __restrict__ erow, const int* __restrict__ ecol,
    const float* __restrict__ eval, int* __restrict__ cursor,
    int* __restrict__ scol, float* __restrict__ sval, int nE)
{
    int i = blockIdx.x * blockDim.x + threadIdx.x;
    int stride = gridDim.x * blockDim.x;
    for (; i < nE; i += stride) {
        int r = erow[i];
        int pos = atomicAdd(&cursor[r], 1);
        scol[pos] = ecol[i];
        sval[pos] = eval[i];
    }
}

// ===========================================================================
// CSR SpMM over fp16 features, fp32 accumulate, fused bias + ReLU, fp32 out.
// One warp per row; each lane owns 4 cols (one 8B half2x2 gather per edge).
// ===========================================================================
__global__ __launch_bounds__(256) void spmm_csr_h_bias_relu_kernel(
    const int* __restrict__ rowptr, const int* __restrict__ scol,
    const float* __restrict__ sval, const __half* __restrict__ X,
    const float* __restrict__ bias, float* __restrict__ out, int M)
{
    int gt = blockIdx.x * blockDim.x + threadIdx.x;
    int r = gt >> 5;
    int lane = gt & 31;
    if (r >= M) return;

    int beg = rowptr[r];
    int end = rowptr[r + 1];

    float4 acc = make_float4(0.f, 0.f, 0.f, 0.f);
    int i = beg;
    for (; i + 4 <= end; i += 4) {
        int c0 = scol[i], c1 = scol[i + 1], c2 = scol[i + 2], c3 = scol[i + 3];
        float v0 = sval[i], v1 = sval[i + 1], v2 = sval[i + 2], v3 = sval[i + 3];
        uint2 r0 = *reinterpret_cast<const uint2*>(X + (size_t)c0 * D + lane * 4);
        uint2 r1 = *reinterpret_cast<const uint2*>(X + (size_t)c1 * D + lane * 4);
        uint2 r2 = *reinterpret_cast<const uint2*>(X + (size_t)c2 * D + lane * 4);
        uint2 r3 = *reinterpret_cast<const uint2*>(X + (size_t)c3 * D + lane * 4);
        float2 a01, a23;
        a01 = __half22float2(*reinterpret_cast<__half2*>(&r0.x));
        a23 = __half22float2(*reinterpret_cast<__half2*>(&r0.y));
        acc.x = fmaf(v0, a01.x, acc.x); acc.y = fmaf(v0, a01.y, acc.y);
        acc.z = fmaf(v0, a23.x, acc.z); acc.w = fmaf(v0, a23.y, acc.w);
        a01 = __half22float2(*reinterpret_cast<__half2*>(&r1.x));
        a23 = __half22float2(*reinterpret_cast<__half2*>(&r1.y));
        acc.x = fmaf(v1, a01.x, acc.x); acc.y = fmaf(v1, a01.y, acc.y);
        acc.z = fmaf(v1, a23.x, acc.z); acc.w = fmaf(v1, a23.y, acc.w);
        a01 = __half22float2(*reinterpret_cast<__half2*>(&r2.x));
        a23 = __half22float2(*reinterpret_cast<__half2*>(&r2.y));
        acc.x = fmaf(v2, a01.x, acc.x); acc.y = fmaf(v2, a01.y, acc.y);
        acc.z = fmaf(v2, a23.x, acc.z); acc.w = fmaf(v2, a23.y, acc.w);
        a01 = __half22float2(*reinterpret_cast<__half2*>(&r3.x));
        a23 = __half22float2(*reinterpret_cast<__half2*>(&r3.y));
        acc.x = fmaf(v3, a01.x, acc.x); acc.y = fmaf(v3, a01.y, acc.y);
        acc.z = fmaf(v3, a23.x, acc.z); acc.w = fmaf(v3, a23.y, acc.w);
    }
    for (; i < end; i++) {
        int c = scol[i];
        float v = sval[i];
        uint2 rr = *reinterpret_cast<const uint2*>(X + (size_t)c * D + lane * 4);
        float2 a01 = __half22float2(*reinterpret_cast<__half2*>(&rr.x));
        float2 a23 = __half22float2(*reinterpret_cast<__half2*>(&rr.y));
        acc.x = fmaf(v, a01.x, acc.x); acc.y = fmaf(v, a01.y, acc.y);
        acc.z = fmaf(v, a23.x, acc.z); acc.w = fmaf(v, a23.y, acc.w);
    }

    const float4 b = *reinterpret_cast<const float4*>(bias + lane * 4);
    float4 o;
    o.x = fmaxf(acc.x + b.x, 0.f);
    o.y = fmaxf(acc.y + b.y, 0.f);
    o.z = fmaxf(acc.z + b.z, 0.f);
    o.w = fmaxf(acc.w + b.w, 0.f);
    *reinterpret_cast<float4*>(out + (size_t)r * D + lane * 4) = o;
}

// ---------------------------------------------------------------------------
// Scalar CSR SpMM + softplus
// ---------------------------------------------------------------------------
__global__ __launch_bounds__(256) void spmm_csr_scalar_softplus_kernel(
    const int* __restrict__ rowptr, const int* __restrict__ scol,
    const float* __restrict__ sval, const float* __restrict__ t,
    const float* __restrict__ bout, float* __restrict__ out, int M)
{
    int r = blockIdx.x * blockDim.x + threadIdx.x;
    if (r >= M) return;
    int beg = rowptr[r], end = rowptr[r + 1];
    float acc = 0.f;
    for (int i = beg; i < end; i++)
        acc = fmaf(sval[i], t[scol[i]], acc);
    float s = acc + bout[0];
    out[r] = fmaxf(s, 0.f) + log1pf(expf(-fabsf(s)));
}

// ---------------------------------------------------------------------------
// t[r] = dot(H[r], Wout) — one warp per row (fp32 H)
// ---------------------------------------------------------------------------
__global__ __launch_bounds__(256) void gemv_kernel(
    const float* __restrict__ H, const float* __restrict__ Wout,
    float* __restrict__ t, int M)
{
    int gtid = blockIdx.x * blockDim.x + threadIdx.x;
    int r = gtid >> 5;
    int lane = gtid & 31;
    if (r >= M) return;

    const float4 h = *reinterpret_cast<const float4*>(H + (size_t)r * D + lane * 4);
    const float4 w = *reinterpret_cast<const float4*>(Wout + lane * 4);
    float s = h.x * w.x + h.y * w.y + h.z * w.z + h.w * w.w;
    #pragma unroll
    for (int o = 16; o > 0; o >>= 1)
        s += __shfl_xor_sync(0xFFFFFFFFu, s, o);
    if (lane == 0) t[r] = s;
}

// ===========================================================================
// Launch
// ===========================================================================
extern "C" void kernel_launch(void* const* d_in, const int* in_sizes, int n_in,
                              void* d_out, int out_size)
{
    const float* x     = (const float*)d_in[0];
    const int*   erow  = (const int*)  d_in[1];
    const int*   ecol  = (const int*)  d_in[2];
    const float* eval  = (const float*)d_in[3];
    const float* W1    = (const float*)d_in[4];
    const float* b1    = (const float*)d_in[5];
    const float* W2    = (const float*)d_in[6];
    const float* b2    = (const float*)d_in[7];
    const float* Wout  = (const float*)d_in[8];
    const float* bout  = (const float*)d_in[9];
    float* out = (float*)d_out;

    const int M  = in_sizes[0] / D;     // 100000
    const int nE = in_sizes[1];         // 1600000

    float *bufA, *tvec, *sval;
    __half* bufH;
    int *cnt, *rowptr, *cursor, *scol, *bsum;
    cudaGetSymbolAddress((void**)&bufA,   g_bufA);
    cudaGetSymbolAddress((void**)&bufH,   g_bufH);
    cudaGetSymbolAddress((void**)&tvec,   g_t);
    cudaGetSymbolAddress((void**)&cnt,    g_cnt);
    cudaGetSymbolAddress((void**)&rowptr, g_rowptr);
    cudaGetSymbolAddress((void**)&cursor, g_cursor);
    cudaGetSymbolAddress((void**)&scol,   g_scol);
    cudaGetSymbolAddress((void**)&sval,   g_sval);
    cudaGetSymbolAddress((void**)&bsum,   g_bsum);

    cudaFuncSetAttribute(gemm_mma_kernel,
                         cudaFuncAttributeMaxDynamicSharedMemorySize, SM_GEMM);

    const int nb = (M + 1023) / 1024;
    const int spmmBlocks = (M * 32 + 255) / 256;
    const int tileBlocks = (M + 127) / 128;
    const int rowBlocks  = (M + 255) / 256;

    // Weight prep (independent of CSR build)
    prep_w_kernel<<<2, 256>>>(W1, W2);

    // CSR build
    zero_int_kernel<<<128, 256>>>(cnt, M);
    hist_kernel<<<1024, 256>>>(erow, cnt, nE);
    scan1_kernel<<<nb, 1024>>>(cnt, cnt, bsum, M);
    scan2_kernel<<<1, 256>>>(bsum, nb);
    scan3_kernel<<<256, 256>>>(cnt, bsum, rowptr, cursor, M, nE);
    scatter_kernel<<<1024, 256>>>(erow, ecol, eval, cursor, scol, sval, nE);

    // Layer 1: h1 = relu(A @ fp16(x @ W1) + b1)
    gemm_mma_kernel<<<tileBlocks, 256, SM_GEMM>>>(x, 0, bufH, M);
    spmm_csr_h_bias_relu_kernel<<<spmmBlocks, 256>>>(rowptr, scol, sval, bufH, b1, bufA, M);

    // Layer 2: h2 = relu(A @ fp16(h1 @ W2) + b2)
    gemm_mma_kernel<<<tileBlocks, 256, SM_GEMM>>>(bufA, 1, bufH, M);
    spmm_csr_h_bias_relu_kernel<<<spmmBlocks, 256>>>(rowptr, scol, sval, bufH, b2, bufA, M);

    // Head: out = softplus(A @ (h2 @ Wout) + bout)
    gemv_kernel<<<spmmBlocks, 256>>>(bufA, Wout, tvec, M);
    spmm_csr_scalar_softplus_kernel<<<rowBlocks, 256>>>(rowptr, scol, sval, tvec, bout, out, M);
}

// round 14
// speedup vs baseline: 2.7807x; 1.0431x over previous
#include <cuda_runtime.h>
#include <cuda_bf16.h>
#include <cuda_fp16.h>
#include <math.h>
#include <stdint.h>

#define N_MAX 100000
#define E_MAX 1600000
#define D 128
#define WP 136                      // padded pitch (bf16 elems) for mma tiles

// Scratch (static __device__ per allocation rules)
__device__ __half g_bufH1[(size_t)N_MAX * D];        // fp16 GEMM output (XW)
__device__ __half g_bufH2[(size_t)N_MAX * D];        // fp16 hidden state
__device__ float g_t[N_MAX];                         // head GEMV output
__device__ int   g_cnt[N_MAX];
__device__ int   g_rowptr[N_MAX + 1];
__device__ int   g_cursor[N_MAX];
__device__ int2  g_epack[E_MAX];                     // packed (col, val)
__device__ int   g_bsum[256];
// Pre-split weights, transposed Bt[n][k], padded pitch WP (bf16 hi/lo)
__device__ unsigned short g_w_hi[2][128 * WP];
__device__ unsigned short g_w_lo[2][128 * WP];

// ===========================================================================
// Weight prep: W[k][n] fp32 -> Bt[n][k] bf16 hi/lo, padded pitch WP
// ===========================================================================
__global__ void prep_w_kernel(const float* __restrict__ W1,
                              const float* __restrict__ W2) {
    const float* W = (blockIdx.x == 0) ? W1 : W2;
    unsigned short* hi = g_w_hi[blockIdx.x];
    unsigned short* lo = g_w_lo[blockIdx.x];
    for (int idx = threadIdx.x; idx < 128 * 128; idx += blockDim.x) {
        int k = idx >> 7, n = idx & 127;
        float w = W[idx];                               // W[k][n]
        __nv_bfloat16 h = __float2bfloat16_rn(w);
        float wl = w - __bfloat162float(h);
        hi[n * WP + k] = __bfloat16_as_ushort(h);
        lo[n * WP + k] = __bfloat16_as_ushort(__float2bfloat16_rn(wl));
    }
}

// ===========================================================================
// GEMM: C16[M,128] = fp16( A[M,128] @ W )  via split-bf16 mma.sync (bf16x3)
// CTA: 128 rows x 128 cols, 256 threads. Warp grid 4x2 -> 32x64 per warp.
// Templated on A dtype (fp32 for layer 1 input x, fp16 for hidden states).
// ===========================================================================
#define SA_HI 0
#define SA_LO (128 * WP * 2)
#define SB_HI (2 * 128 * WP * 2)
#define SB_LO (3 * 128 * WP * 2)
#define SM_GEMM (4 * 128 * WP * 2)     // 139264 B

__device__ __forceinline__ float2 load2(const float* p) {
    return *reinterpret_cast<const float2*>(p);
}
__device__ __forceinline__ float2 load2(const __half* p) {
    return __half22float2(*reinterpret_cast<const __half2*>(p));
}

#define MMA_BF16(c, a, b) \
    asm volatile( \
        "mma.sync.aligned.m16n8k16.row.col.f32.bf16.bf16.f32 " \
        "{%0,%1,%2,%3}, {%4,%5,%6,%7}, {%8,%9}, {%0,%1,%2,%3};" \
        : "+f"((c)[0]), "+f"((c)[1]), "+f"((c)[2]), "+f"((c)[3]) \
        : "r"((a)[0]), "r"((a)[1]), "r"((a)[2]), "r"((a)[3]), \
          "r"((b)[0]), "r"((b)[1]))

template<typename TIN>
__global__ __launch_bounds__(256) void gemm_mma_kernel(
    const TIN* __restrict__ A, int widx, __half* __restrict__ C16, int M)
{
    extern __shared__ char smem[];
    const int tid = threadIdx.x;
    const int wid = tid >> 5, lane = tid & 31;
    const int row0 = blockIdx.x * 128;

    // Stage W tiles (linear copy of padded images)
    {
        const uint4* whi = reinterpret_cast<const uint4*>(g_w_hi[widx]);
        const uint4* wlo = reinterpret_cast<const uint4*>(g_w_lo[widx]);
        uint4* dh = reinterpret_cast<uint4*>(smem + SB_HI);
        uint4* dl = reinterpret_cast<uint4*>(smem + SB_LO);
        for (int i = tid; i < (128 * WP * 2) / 16; i += 256) {
            dh[i] = whi[i];
            dl[i] = wlo[i];
        }
    }
    // Stage A: -> bf16 hi/lo
    {
        unsigned short* sAhi = reinterpret_cast<unsigned short*>(smem + SA_HI);
        unsigned short* sAlo = reinterpret_cast<unsigned short*>(smem + SA_LO);
        for (int idx = tid; idx < 128 * 64; idx += 256) {
            int row = idx >> 6;
            int cp  = (idx & 63) << 1;
            int gr  = row0 + row;
            float2 a = make_float2(0.f, 0.f);
            if (gr < M)
                a = load2(A + (size_t)gr * D + cp);
            __nv_bfloat16 h0 = __float2bfloat16_rn(a.x);
            __nv_bfloat16 h1 = __float2bfloat16_rn(a.y);
            __nv_bfloat16 l0 = __float2bfloat16_rn(a.x - __bfloat162float(h0));
            __nv_bfloat16 l1 = __float2bfloat16_rn(a.y - __bfloat162float(h1));
            int o = row * WP + cp;
            *reinterpret_cast<uint32_t*>(sAhi + o) =
                (uint32_t)__bfloat16_as_ushort(h0) |
                ((uint32_t)__bfloat16_as_ushort(h1) << 16);
            *reinterpret_cast<uint32_t*>(sAlo + o) =
                (uint32_t)__bfloat16_as_ushort(l0) |
                ((uint32_t)__bfloat16_as_ushort(l1) << 16);
        }
    }
    __syncthreads();

    const int wm = (wid & 3) * 32;       // warp row base
    const int wn = (wid >> 2) * 64;      // warp col base
    const int qr = lane >> 2;            // 0..7
    const int qc = (lane & 3) * 2;       // 0,2,4,6

    const uint32_t* pAh = reinterpret_cast<const uint32_t*>(smem + SA_HI);
    const uint32_t* pAl = reinterpret_cast<const uint32_t*>(smem + SA_LO);
    const uint32_t* pBh = reinterpret_cast<const uint32_t*>(smem + SB_HI);
    const uint32_t* pBl = reinterpret_cast<const uint32_t*>(smem + SB_LO);
    const int WPW = WP / 2;              // 68 words per row

    float acc[2][8][4];
    #pragma unroll
    for (int mt = 0; mt < 2; mt++)
        #pragma unroll
        for (int nt = 0; nt < 8; nt++)
            #pragma unroll
            for (int j = 0; j < 4; j++) acc[mt][nt][j] = 0.f;

    #pragma unroll
    for (int ks = 0; ks < 8; ks++) {
        const int kw = (ks * 16 + qc) >> 1;
        uint32_t ah[2][4], al[2][4];
        #pragma unroll
        for (int mt = 0; mt < 2; mt++) {
            int r = wm + mt * 16 + qr;
            int w0 = r * WPW + kw;
            int w1 = (r + 8) * WPW + kw;
            ah[mt][0] = pAh[w0];     ah[mt][1] = pAh[w1];
            ah[mt][2] = pAh[w0 + 4]; ah[mt][3] = pAh[w1 + 4];
            al[mt][0] = pAl[w0];     al[mt][1] = pAl[w1];
            al[mt][2] = pAl[w0 + 4]; al[mt][3] = pAl[w1 + 4];
        }
        uint32_t bh[8][2], bl[8][2];
        #pragma unroll
        for (int nt = 0; nt < 8; nt++) {
            int n = wn + nt * 8 + qr;
            int w0 = n * WPW + kw;
            bh[nt][0] = pBh[w0]; bh[nt][1] = pBh[w0 + 4];
            bl[nt][0] = pBl[w0]; bl[nt][1] = pBl[w0 + 4];
        }
        #pragma unroll
        for (int mt = 0; mt < 2; mt++)
            #pragma unroll
            for (int nt = 0; nt < 8; nt++) {
                MMA_BF16(acc[mt][nt], ah[mt], bh[nt]);
                MMA_BF16(acc[mt][nt], ah[mt], bl[nt]);
                MMA_BF16(acc[mt][nt], al[mt], bh[nt]);
            }
    }

    // Epilogue: fp16 stores
    #pragma unroll
    for (int mt = 0; mt < 2; mt++) {
        int r = row0 + wm + mt * 16 + qr;
        #pragma unroll
        for (int nt = 0; nt < 8; nt++) {
            int col = wn + nt * 8 + qc;
            if (r < M)
                *reinterpret_cast<__half2*>(C16 + (size_t)r * D + col) =
                    __floats2half2_rn(acc[mt][nt][0], acc[mt][nt][1]);
            if (r + 8 < M)
                *reinterpret_cast<__half2*>(C16 + (size_t)(r + 8) * D + col) =
                    __floats2half2_rn(acc[mt][nt][2], acc[mt][nt][3]);
        }
    }
}

// ===========================================================================
// CSR build
// ===========================================================================
__global__ void zero_int_kernel(int* __restrict__ p, int n) {
    int i = blockIdx.x * blockDim.x + threadIdx.x;
    int stride = gridDim.x * blockDim.x;
    for (; i < n; i += stride) p[i] = 0;
}

__global__ void hist_kernel(const int* __restrict__ erow, int* __restrict__ cnt, int nE) {
    int i = blockIdx.x * blockDim.x + threadIdx.x;
    int stride = gridDim.x * blockDim.x;
    for (; i < nE; i += stride) atomicAdd(&cnt[erow[i]], 1);
}

__global__ __launch_bounds__(1024) void scan1_kernel(
    const int* __restrict__ cnt, int* __restrict__ excl, int* __restrict__ bsum, int n)
{
    __shared__ int s[1024];
    int tid = threadIdx.x;
    int i = blockIdx.x * 1024 + tid;
    int v = (i < n) ? cnt[i] : 0;
    s[tid] = v;
    __syncthreads();
    #pragma unroll
    for (int o = 1; o < 1024; o <<= 1) {
        int t = (tid >= o) ? s[tid - o] : 0;
        __syncthreads();
        s[tid] += t;
        __syncthreads();
    }
    if (i < n) excl[i] = s[tid] - v;
    if (tid == 1023) bsum[blockIdx.x] = s[1023];
}

__global__ __launch_bounds__(256) void scan2_kernel(int* __restrict__ bsum, int nb) {
    __shared__ int s[256];
    int tid = threadIdx.x;
    int v = (tid < nb) ? bsum[tid] : 0;
    s[tid] = v;
    __syncthreads();
    #pragma unroll
    for (int o = 1; o < 256; o <<= 1) {
        int t = (tid >= o) ? s[tid - o] : 0;
        __syncthreads();
        s[tid] += t;
        __syncthreads();
    }
    if (tid < nb) bsum[tid] = s[tid] - v;
}

__global__ void scan3_kernel(
    const int* __restrict__ excl, const int* __restrict__ bsum,
    int* __restrict__ rowptr, int* __restrict__ cursor, int n, int nE)
{
    int i = blockIdx.x * blockDim.x + threadIdx.x;
    int stride = gridDim.x * blockDim.x;
    for (; i <= n; i += stride) {
        if (i < n) {
            int rp = excl[i] + bsum[i >> 10];
            rowptr[i] = rp;
            cursor[i] = rp;
        } else {
            rowptr[n] = nE;
        }
    }
}

__global__ void scatter_kernel(
    const int* __restrict__ erow, const int* __restrict__ ecol,
    const float* __restrict__ eval, int* __restrict__ cursor,
    int2* __restrict__ epack, int nE)
{
    int i = blockIdx.x * blockDim.x + threadIdx.x;
    int stride = gridDim.x * blockDim.x;
    for (; i < nE; i += stride) {
        int r = erow[i];
        int pos = atomicAdd(&cursor[r], 1);
        epack[pos] = make_int2(ecol[i], __float_as_int(eval[i]));
    }
}

// ===========================================================================
// CSR SpMM over fp16 features, fp32 accumulate, fused bias + ReLU, fp16 out.
// One warp per row; each lane owns 4 cols (8B gather per edge). Unroll 8.
// ===========================================================================
#define SPMM_FMA(acc, v, g) do { \
    float2 _a01 = __half22float2(*reinterpret_cast<__half2*>(&(g).x)); \
    float2 _a23 = __half22float2(*reinterpret_cast<__half2*>(&(g).y)); \
    (acc).x = fmaf((v), _a01.x, (acc).x); (acc).y = fmaf((v), _a01.y, (acc).y); \
    (acc).z = fmaf((v), _a23.x, (acc).z); (acc).w = fmaf((v), _a23.y, (acc).w); \
} while (0)

__global__ __launch_bounds__(256) void spmm_csr_h_bias_relu_kernel(
    const int* __restrict__ rowptr, const int2* __restrict__ epack,
    const __half* __restrict__ X,
    const float* __restrict__ bias, __half* __restrict__ out, int M)
{
    int gt = blockIdx.x * blockDim.x + threadIdx.x;
    int r = gt >> 5;
    int lane = gt & 31;
    if (r >= M) return;

    int beg = rowptr[r];
    int end = rowptr[r + 1];

    float4 acc = make_float4(0.f, 0.f, 0.f, 0.f);
    int i = beg;
    for (; i + 8 <= end; i += 8) {
        int2 e[8];
        #pragma unroll
        for (int j = 0; j < 8; j++) e[j] = epack[i + j];
        uint2 g[8];
        #pragma unroll
        for (int j = 0; j < 8; j++)
            g[j] = *reinterpret_cast<const uint2*>(X + (size_t)e[j].x * D + lane * 4);
        #pragma unroll
        for (int j = 0; j < 8; j++)
            SPMM_FMA(acc, __int_as_float(e[j].y), g[j]);
    }
    for (; i < end; i++) {
        int2 e = epack[i];
        uint2 g = *reinterpret_cast<const uint2*>(X + (size_t)e.x * D + lane * 4);
        SPMM_FMA(acc, __int_as_float(e.y), g);
    }

    const float4 b = *reinterpret_cast<const float4*>(bias + lane * 4);
    __half2 o01 = __floats2half2_rn(fmaxf(acc.x + b.x, 0.f), fmaxf(acc.y + b.y, 0.f));
    __half2 o23 = __floats2half2_rn(fmaxf(acc.z + b.z, 0.f), fmaxf(acc.w + b.w, 0.f));
    uint2 ov;
    ov.x = *reinterpret_cast<uint32_t*>(&o01);
    ov.y = *reinterpret_cast<uint32_t*>(&o23);
    *reinterpret_cast<uint2*>(out + (size_t)r * D + lane * 4) = ov;
}

// ---------------------------------------------------------------------------
// Scalar CSR SpMM + softplus
// ---------------------------------------------------------------------------
__global__ __launch_bounds__(256) void spmm_csr_scalar_softplus_kernel(
    const int* __restrict__ rowptr, const int2* __restrict__ epack,
    const float* __restrict__ t,
    const float* __restrict__ bout, float* __restrict__ out, int M)
{
    int r = blockIdx.x * blockDim.x + threadIdx.x;
    if (r >= M) return;
    int beg = rowptr[r], end = rowptr[r + 1];
    float acc = 0.f;
    for (int i = beg; i < end; i++) {
        int2 e = epack[i];
        acc = fmaf(__int_as_float(e.y), t[e.x], acc);
    }
    float s = acc + bout[0];
    out[r] = fmaxf(s, 0.f) + log1pf(expf(-fabsf(s)));
}

// ---------------------------------------------------------------------------
// t[r] = dot(H[r], Wout) — one warp per row (fp16 H)
// ---------------------------------------------------------------------------
__global__ __launch_bounds__(256) void gemv_kernel(
    const __half* __restrict__ H, const float* __restrict__ Wout,
    float* __restrict__ t, int M)
{
    int gtid = blockIdx.x * blockDim.x + threadIdx.x;
    int r = gtid >> 5;
    int lane = gtid & 31;
    if (r >= M) return;

    uint2 hv = *reinterpret_cast<const uint2*>(H + (size_t)r * D + lane * 4);
    float2 h01 = __half22float2(*reinterpret_cast<__half2*>(&hv.x));
    float2 h23 = __half22float2(*reinterpret_cast<__half2*>(&hv.y));
    const float4 w = *reinterpret_cast<const float4*>(Wout + lane * 4);
    float s = h01.x * w.x + h01.y * w.y + h23.x * w.z + h23.y * w.w;
    #pragma unroll
    for (int o = 16; o > 0; o >>= 1)
        s += __shfl_xor_sync(0xFFFFFFFFu, s, o);
    if (lane == 0) t[r] = s;
}

// ===========================================================================
// Launch
// ===========================================================================
extern "C" void kernel_launch(void* const* d_in, const int* in_sizes, int n_in,
                              void* d_out, int out_size)
{
    const float* x     = (const float*)d_in[0];
    const int*   erow  = (const int*)  d_in[1];
    const int*   ecol  = (const int*)  d_in[2];
    const float* eval  = (const float*)d_in[3];
    const float* W1    = (const float*)d_in[4];
    const float* b1    = (const float*)d_in[5];
    const float* W2    = (const float*)d_in[6];
    const float* b2    = (const float*)d_in[7];
    const float* Wout  = (const float*)d_in[8];
    const float* bout  = (const float*)d_in[9];
    float* out = (float*)d_out;

    const int M  = in_sizes[0] / D;     // 100000
    const int nE = in_sizes[1];         // 1600000

    float *tvec;
    __half *bufH1, *bufH2;
    int *cnt, *rowptr, *cursor, *bsum;
    int2* epack;
    cudaGetSymbolAddress((void**)&bufH1,  g_bufH1);
    cudaGetSymbolAddress((void**)&bufH2,  g_bufH2);
    cudaGetSymbolAddress((void**)&tvec,   g_t);
    cudaGetSymbolAddress((void**)&cnt,    g_cnt);
    cudaGetSymbolAddress((void**)&rowptr, g_rowptr);
    cudaGetSymbolAddress((void**)&cursor, g_cursor);
    cudaGetSymbolAddress((void**)&epack,  g_epack);
    cudaGetSymbolAddress((void**)&bsum,   g_bsum);

    cudaFuncSetAttribute(gemm_mma_kernel<float>,
                         cudaFuncAttributeMaxDynamicSharedMemorySize, SM_GEMM);
    cudaFuncSetAttribute(gemm_mma_kernel<__half>,
                         cudaFuncAttributeMaxDynamicSharedMemorySize, SM_GEMM);

    const int nb = (M + 1023) / 1024;
    const int spmmBlocks = (M * 32 + 255) / 256;
    const int tileBlocks = (M + 127) / 128;
    const int rowBlocks  = (M + 255) / 256;

    // Weight prep (independent of CSR build)
    prep_w_kernel<<<2, 256>>>(W1, W2);

    // CSR build
    zero_int_kernel<<<128, 256>>>(cnt, M);
    hist_kernel<<<1024, 256>>>(erow, cnt, nE);
    scan1_kernel<<<nb, 1024>>>(cnt, cnt, bsum, M);
    scan2_kernel<<<1, 256>>>(bsum, nb);
    scan3_kernel<<<256, 256>>>(cnt, bsum, rowptr, cursor, M, nE);
    scatter_kernel<<<1024, 256>>>(erow, ecol, eval, cursor, epack, nE);

    // Layer 1: h1 = relu(A @ fp16(x @ W1) + b1)
    gemm_mma_kernel<float><<<tileBlocks, 256, SM_GEMM>>>(x, 0, bufH1, M);
    spmm_csr_h_bias_relu_kernel<<<spmmBlocks, 256>>>(rowptr, epack, bufH1, b1, bufH2, M);

    // Layer 2: h2 = relu(A @ fp16(h1 @ W2) + b2)
    gemm_mma_kernel<__half><<<tileBlocks, 256, SM_GEMM>>>(bufH2, 1, bufH1, M);
    spmm_csr_h_bias_relu_kernel<<<spmmBlocks, 256>>>(rowptr, epack, bufH1, b2, bufH2, M);

    // Head: out = softplus(A @ (h2 @ Wout) + bout)
    gemv_kernel<<<spmmBlocks, 256>>>(bufH2, Wout, tvec, M);
    spmm_csr_scalar_softplus_kernel<<<rowBlocks, 256>>>(rowptr, epack, tvec, bout, out, M);
}

// round 15
// speedup vs baseline: 2.8089x; 1.0101x over previous
#include <cuda_runtime.h>
#include <cuda_bf16.h>
#include <cuda_fp16.h>
#include <math.h>
#include <stdint.h>

#define N_MAX 100000
#define E_MAX 1600000
#define D 128
#define WP 136                      // padded pitch (bf16 elems) for mma tiles

// Scratch (static __device__ per allocation rules)
__device__ __half g_bufH1[(size_t)N_MAX * D];        // fp16 GEMM output (XW)
__device__ __half g_bufH2[(size_t)N_MAX * D];        // fp16 hidden state h1
__device__ float g_t[N_MAX];                         // fused head output
__device__ int   g_cnt[N_MAX];
__device__ int   g_rowptr[N_MAX + 1];
__device__ int   g_cursor[N_MAX];
__device__ __align__(16) int2 g_epack[E_MAX];        // packed (col, val)
__device__ int   g_bsum[256];
// Pre-split weights, transposed Bt[n][k], padded pitch WP (bf16 hi/lo)
__device__ unsigned short g_w_hi[2][128 * WP];
__device__ unsigned short g_w_lo[2][128 * WP];

// ===========================================================================
// Combo: blocks 0-1 prep weights (W -> Bt bf16 hi/lo), blocks 2+ zero cnt
// ===========================================================================
__global__ void prep_zero_kernel(const float* __restrict__ W1,
                                 const float* __restrict__ W2,
                                 int* __restrict__ cnt, int n) {
    if (blockIdx.x < 2) {
        const float* W = (blockIdx.x == 0) ? W1 : W2;
        unsigned short* hi = g_w_hi[blockIdx.x];
        unsigned short* lo = g_w_lo[blockIdx.x];
        for (int idx = threadIdx.x; idx < 128 * 128; idx += blockDim.x) {
            int k = idx >> 7, nn = idx & 127;
            float w = W[idx];
            __nv_bfloat16 h = __float2bfloat16_rn(w);
            float wl = w - __bfloat162float(h);
            hi[nn * WP + k] = __bfloat16_as_ushort(h);
            lo[nn * WP + k] = __bfloat16_as_ushort(__float2bfloat16_rn(wl));
        }
    } else {
        int i = (blockIdx.x - 2) * blockDim.x + threadIdx.x;
        int stride = (gridDim.x - 2) * blockDim.x;
        for (; i < n; i += stride) cnt[i] = 0;
    }
}

// ===========================================================================
// GEMM: C16[M,128] = fp16( A[M,128] @ W )  via split-bf16 mma.sync (bf16x3)
// ===========================================================================
#define SA_HI 0
#define SA_LO (128 * WP * 2)
#define SB_HI (2 * 128 * WP * 2)
#define SB_LO (3 * 128 * WP * 2)
#define SM_GEMM (4 * 128 * WP * 2)     // 139264 B

__device__ __forceinline__ float2 load2(const float* p) {
    return *reinterpret_cast<const float2*>(p);
}
__device__ __forceinline__ float2 load2(const __half* p) {
    return __half22float2(*reinterpret_cast<const __half2*>(p));
}

#define MMA_BF16(c, a, b) \
    asm volatile( \
        "mma.sync.aligned.m16n8k16.row.col.f32.bf16.bf16.f32 " \
        "{%0,%1,%2,%3}, {%4,%5,%6,%7}, {%8,%9}, {%0,%1,%2,%3};" \
        : "+f"((c)[0]), "+f"((c)[1]), "+f"((c)[2]), "+f"((c)[3]) \
        : "r"((a)[0]), "r"((a)[1]), "r"((a)[2]), "r"((a)[3]), \
          "r"((b)[0]), "r"((b)[1]))

template<typename TIN>
__global__ __launch_bounds__(256) void gemm_mma_kernel(
    const TIN* __restrict__ A, int widx, __half* __restrict__ C16, int M)
{
    extern __shared__ char smem[];
    const int tid = threadIdx.x;
    const int wid = tid >> 5, lane = tid & 31;
    const int row0 = blockIdx.x * 128;

    {
        const uint4* whi = reinterpret_cast<const uint4*>(g_w_hi[widx]);
        const uint4* wlo = reinterpret_cast<const uint4*>(g_w_lo[widx]);
        uint4* dh = reinterpret_cast<uint4*>(smem + SB_HI);
        uint4* dl = reinterpret_cast<uint4*>(smem + SB_LO);
        for (int i = tid; i < (128 * WP * 2) / 16; i += 256) {
            dh[i] = whi[i];
            dl[i] = wlo[i];
        }
    }
    {
        unsigned short* sAhi = reinterpret_cast<unsigned short*>(smem + SA_HI);
        unsigned short* sAlo = reinterpret_cast<unsigned short*>(smem + SA_LO);
        for (int idx = tid; idx < 128 * 64; idx += 256) {
            int row = idx >> 6;
            int cp  = (idx & 63) << 1;
            int gr  = row0 + row;
            float2 a = make_float2(0.f, 0.f);
            if (gr < M)
                a = load2(A + (size_t)gr * D + cp);
            __nv_bfloat16 h0 = __float2bfloat16_rn(a.x);
            __nv_bfloat16 h1 = __float2bfloat16_rn(a.y);
            __nv_bfloat16 l0 = __float2bfloat16_rn(a.x - __bfloat162float(h0));
            __nv_bfloat16 l1 = __float2bfloat16_rn(a.y - __bfloat162float(h1));
            int o = row * WP + cp;
            *reinterpret_cast<uint32_t*>(sAhi + o) =
                (uint32_t)__bfloat16_as_ushort(h0) |
                ((uint32_t)__bfloat16_as_ushort(h1) << 16);
            *reinterpret_cast<uint32_t*>(sAlo + o) =
                (uint32_t)__bfloat16_as_ushort(l0) |
                ((uint32_t)__bfloat16_as_ushort(l1) << 16);
        }
    }
    __syncthreads();

    const int wm = (wid & 3) * 32;
    const int wn = (wid >> 2) * 64;
    const int qr = lane >> 2;
    const int qc = (lane & 3) * 2;

    const uint32_t* pAh = reinterpret_cast<const uint32_t*>(smem + SA_HI);
    const uint32_t* pAl = reinterpret_cast<const uint32_t*>(smem + SA_LO);
    const uint32_t* pBh = reinterpret_cast<const uint32_t*>(smem + SB_HI);
    const uint32_t* pBl = reinterpret_cast<const uint32_t*>(smem + SB_LO);
    const int WPW = WP / 2;

    float acc[2][8][4];
    #pragma unroll
    for (int mt = 0; mt < 2; mt++)
        #pragma unroll
        for (int nt = 0; nt < 8; nt++)
            #pragma unroll
            for (int j = 0; j < 4; j++) acc[mt][nt][j] = 0.f;

    #pragma unroll
    for (int ks = 0; ks < 8; ks++) {
        const int kw = (ks * 16 + qc) >> 1;
        uint32_t ah[2][4], al[2][4];
        #pragma unroll
        for (int mt = 0; mt < 2; mt++) {
            int r = wm + mt * 16 + qr;
            int w0 = r * WPW + kw;
            int w1 = (r + 8) * WPW + kw;
            ah[mt][0] = pAh[w0];     ah[mt][1] = pAh[w1];
            ah[mt][2] = pAh[w0 + 4]; ah[mt][3] = pAh[w1 + 4];
            al[mt][0] = pAl[w0];     al[mt][1] = pAl[w1];
            al[mt][2] = pAl[w0 + 4]; al[mt][3] = pAl[w1 + 4];
        }
        uint32_t bh[8][2], bl[8][2];
        #pragma unroll
        for (int nt = 0; nt < 8; nt++) {
            int n = wn + nt * 8 + qr;
            int w0 = n * WPW + kw;
            bh[nt][0] = pBh[w0]; bh[nt][1] = pBh[w0 + 4];
            bl[nt][0] = pBl[w0]; bl[nt][1] = pBl[w0 + 4];
        }
        #pragma unroll
        for (int mt = 0; mt < 2; mt++)
            #pragma unroll
            for (int nt = 0; nt < 8; nt++) {
                MMA_BF16(acc[mt][nt], ah[mt], bh[nt]);
                MMA_BF16(acc[mt][nt], ah[mt], bl[nt]);
                MMA_BF16(acc[mt][nt], al[mt], bh[nt]);
            }
    }

    #pragma unroll
    for (int mt = 0; mt < 2; mt++) {
        int r = row0 + wm + mt * 16 + qr;
        #pragma unroll
        for (int nt = 0; nt < 8; nt++) {
            int col = wn + nt * 8 + qc;
            if (r < M)
                *reinterpret_cast<__half2*>(C16 + (size_t)r * D + col) =
                    __floats2half2_rn(acc[mt][nt][0], acc[mt][nt][1]);
            if (r + 8 < M)
                *reinterpret_cast<__half2*>(C16 + (size_t)(r + 8) * D + col) =
                    __floats2half2_rn(acc[mt][nt][2], acc[mt][nt][3]);
        }
    }
}

// ===========================================================================
// CSR build
// ===========================================================================
__global__ void hist_kernel(const int* __restrict__ erow, int* __restrict__ cnt, int nE) {
    int i = blockIdx.x * blockDim.x + threadIdx.x;
    int stride = gridDim.x * blockDim.x;
    for (; i < nE; i += stride) atomicAdd(&cnt[erow[i]], 1);
}

// Two-level shfl scan (2 syncs): exclusive partials + block sums
__global__ __launch_bounds__(1024) void scan1_kernel(
    const int* __restrict__ cnt, int* __restrict__ excl, int* __restrict__ bsum, int n)
{
    __shared__ int wsum[32];
    int tid = threadIdx.x;
    int lane = tid & 31, wid = tid >> 5;
    int i = blockIdx.x * 1024 + tid;
    int v = (i < n) ? cnt[i] : 0;
    int s = v;
    #pragma unroll
    for (int o = 1; o < 32; o <<= 1) {
        int t = __shfl_up_sync(0xFFFFFFFFu, s, o);
        if (lane >= o) s += t;
    }
    if (lane == 31) wsum[wid] = s;
    __syncthreads();
    if (wid == 0) {
        int w = wsum[lane];
        #pragma unroll
        for (int o = 1; o < 32; o <<= 1) {
            int t = __shfl_up_sync(0xFFFFFFFFu, w, o);
            if (lane >= o) w += t;
        }
        wsum[lane] = w;
    }
    __syncthreads();
    int incl = s + (wid > 0 ? wsum[wid - 1] : 0);
    if (i < n) excl[i] = incl - v;
    if (tid == 1023) bsum[blockIdx.x] = incl;
}

// Exclusive scan of <=128 block sums, 128 threads, shfl-based
__global__ __launch_bounds__(128) void scan2_kernel(int* __restrict__ bsum, int nb) {
    __shared__ int wsum[4];
    int tid = threadIdx.x;
    int lane = tid & 31, wid = tid >> 5;
    int v = (tid < nb) ? bsum[tid] : 0;
    int s = v;
    #pragma unroll
    for (int o = 1; o < 32; o <<= 1) {
        int t = __shfl_up_sync(0xFFFFFFFFu, s, o);
        if (lane >= o) s += t;
    }
    if (lane == 31) wsum[wid] = s;
    __syncthreads();
    int base = 0;
    #pragma unroll
    for (int k = 0; k < 4; k++)
        if (k < wid) base += wsum[k];
    if (tid < nb) bsum[tid] = base + s - v;   // exclusive
}

__global__ void scan3_kernel(
    const int* __restrict__ excl, const int* __restrict__ bsum,
    int* __restrict__ rowptr, int* __restrict__ cursor, int n, int nE)
{
    int i = blockIdx.x * blockDim.x + threadIdx.x;
    int stride = gridDim.x * blockDim.x;
    for (; i <= n; i += stride) {
        if (i < n) {
            int rp = excl[i] + bsum[i >> 10];
            rowptr[i] = rp;
            cursor[i] = rp;
        } else {
            rowptr[n] = nE;
        }
    }
}

__global__ void scatter_kernel(
    const int* __restrict__ erow, const int* __restrict__ ecol,
    const float* __restrict__ eval, int* __restrict__ cursor,
    int2* __restrict__ epack, int nE)
{
    int i = blockIdx.x * blockDim.x + threadIdx.x;
    int stride = gridDim.x * blockDim.x;
    for (; i < nE; i += stride) {
        int r = erow[i];
        int pos = atomicAdd(&cursor[r], 1);
        epack[pos] = make_int2(ecol[i], __float_as_int(eval[i]));
    }
}

// ===========================================================================
// SpMM core: fp16 gathers, fp32 accumulate. One warp per row, 4 cols/lane.
// Aligned int4 epack loads (2 edges each) with odd-start peel.
// ===========================================================================
#define SPMM_FMA(acc, v, g) do { \
    float2 _a01 = __half22float2(*reinterpret_cast<__half2*>(&(g).x)); \
    float2 _a23 = __half22float2(*reinterpret_cast<__half2*>(&(g).y)); \
    (acc).x = fmaf((v), _a01.x, (acc).x); (acc).y = fmaf((v), _a01.y, (acc).y); \
    (acc).z = fmaf((v), _a23.x, (acc).z); (acc).w = fmaf((v), _a23.y, (acc).w); \
} while (0)

__device__ __forceinline__ float4 spmm_row_acc(
    const int2* __restrict__ epack, const __half* __restrict__ X,
    int beg, int end, int lane)
{
    float4 acc = make_float4(0.f, 0.f, 0.f, 0.f);
    int i = beg;
    if ((i & 1) && i < end) {                     // peel to 16B alignment
        int2 e = epack[i];
        uint2 g = *reinterpret_cast<const uint2*>(X + (size_t)e.x * D + lane * 4);
        SPMM_FMA(acc, __int_as_float(e.y), g);
        i++;
    }
    for (; i + 8 <= end; i += 8) {
        int4 ep0 = *reinterpret_cast<const int4*>(epack + i);
        int4 ep1 = *reinterpret_cast<const int4*>(epack + i + 2);
        int4 ep2 = *reinterpret_cast<const int4*>(epack + i + 4);
        int4 ep3 = *reinterpret_cast<const int4*>(epack + i + 6);
        uint2 g[8];
        g[0] = *reinterpret_cast<const uint2*>(X + (size_t)ep0.x * D + lane * 4);
        g[1] = *reinterpret_cast<const uint2*>(X + (size_t)ep0.z * D + lane * 4);
        g[2] = *reinterpret_cast<const uint2*>(X + (size_t)ep1.x * D + lane * 4);
        g[3] = *reinterpret_cast<const uint2*>(X + (size_t)ep1.z * D + lane * 4);
        g[4] = *reinterpret_cast<const uint2*>(X + (size_t)ep2.x * D + lane * 4);
        g[5] = *reinterpret_cast<const uint2*>(X + (size_t)ep2.z * D + lane * 4);
        g[6] = *reinterpret_cast<const uint2*>(X + (size_t)ep3.x * D + lane * 4);
        g[7] = *reinterpret_cast<const uint2*>(X + (size_t)ep3.z * D + lane * 4);
        SPMM_FMA(acc, __int_as_float(ep0.y), g[0]);
        SPMM_FMA(acc, __int_as_float(ep0.w), g[1]);
        SPMM_FMA(acc, __int_as_float(ep1.y), g[2]);
        SPMM_FMA(acc, __int_as_float(ep1.w), g[3]);
        SPMM_FMA(acc, __int_as_float(ep2.y), g[4]);
        SPMM_FMA(acc, __int_as_float(ep2.w), g[5]);
        SPMM_FMA(acc, __int_as_float(ep3.y), g[6]);
        SPMM_FMA(acc, __int_as_float(ep3.w), g[7]);
    }
    for (; i + 2 <= end; i += 2) {
        int4 ep = *reinterpret_cast<const int4*>(epack + i);
        uint2 g0 = *reinterpret_cast<const uint2*>(X + (size_t)ep.x * D + lane * 4);
        uint2 g1 = *reinterpret_cast<const uint2*>(X + (size_t)ep.z * D + lane * 4);
        SPMM_FMA(acc, __int_as_float(ep.y), g0);
        SPMM_FMA(acc, __int_as_float(ep.w), g1);
    }
    if (i < end) {
        int2 e = epack[i];
        uint2 g = *reinterpret_cast<const uint2*>(X + (size_t)e.x * D + lane * 4);
        SPMM_FMA(acc, __int_as_float(e.y), g);
    }
    return acc;
}

// Layer-1 SpMM: out = fp16(relu(A@X + bias))
__global__ __launch_bounds__(256) void spmm_csr_h_bias_relu_kernel(
    const int* __restrict__ rowptr, const int2* __restrict__ epack,
    const __half* __restrict__ X,
    const float* __restrict__ bias, __half* __restrict__ out, int M)
{
    int gt = blockIdx.x * blockDim.x + threadIdx.x;
    int r = gt >> 5;
    int lane = gt & 31;
    if (r >= M) return;

    float4 acc = spmm_row_acc(epack, X, rowptr[r], rowptr[r + 1], lane);

    const float4 b = *reinterpret_cast<const float4*>(bias + lane * 4);
    __half2 o01 = __floats2half2_rn(fmaxf(acc.x + b.x, 0.f), fmaxf(acc.y + b.y, 0.f));
    __half2 o23 = __floats2half2_rn(fmaxf(acc.z + b.z, 0.f), fmaxf(acc.w + b.w, 0.f));
    uint2 ov;
    ov.x = *reinterpret_cast<uint32_t*>(&o01);
    ov.y = *reinterpret_cast<uint32_t*>(&o23);
    *reinterpret_cast<uint2*>(out + (size_t)r * D + lane * 4) = ov;
}

// Layer-2 SpMM with fused head GEMV: t[r] = dot(relu(A@X + bias), Wout)
// (h2 never materialized)
__global__ __launch_bounds__(256) void spmm_csr_relu_gemv_kernel(
    const int* __restrict__ rowptr, const int2* __restrict__ epack,
    const __half* __restrict__ X,
    const float* __restrict__ bias, const float* __restrict__ Wout,
    float* __restrict__ t, int M)
{
    int gt = blockIdx.x * blockDim.x + threadIdx.x;
    int r = gt >> 5;
    int lane = gt & 31;
    if (r >= M) return;

    float4 acc = spmm_row_acc(epack, X, rowptr[r], rowptr[r + 1], lane);

    const float4 b = *reinterpret_cast<const float4*>(bias + lane * 4);
    const float4 w = *reinterpret_cast<const float4*>(Wout + lane * 4);
    float s = fmaxf(acc.x + b.x, 0.f) * w.x
            + fmaxf(acc.y + b.y, 0.f) * w.y
            + fmaxf(acc.z + b.z, 0.f) * w.z
            + fmaxf(acc.w + b.w, 0.f) * w.w;
    #pragma unroll
    for (int o = 16; o > 0; o >>= 1)
        s += __shfl_xor_sync(0xFFFFFFFFu, s, o);
    if (lane == 0) t[r] = s;
}

// ---------------------------------------------------------------------------
// Scalar CSR SpMM + softplus
// ---------------------------------------------------------------------------
__global__ __launch_bounds__(256) void spmm_csr_scalar_softplus_kernel(
    const int* __restrict__ rowptr, const int2* __restrict__ epack,
    const float* __restrict__ t,
    const float* __restrict__ bout, float* __restrict__ out, int M)
{
    int r = blockIdx.x * blockDim.x + threadIdx.x;
    if (r >= M) return;
    int beg = rowptr[r], end = rowptr[r + 1];
    float acc = 0.f;
    for (int i = beg; i < end; i++) {
        int2 e = epack[i];
        acc = fmaf(__int_as_float(e.y), t[e.x], acc);
    }
    float s = acc + bout[0];
    out[r] = fmaxf(s, 0.f) + log1pf(expf(-fabsf(s)));
}

// ===========================================================================
// Launch
// ===========================================================================
extern "C" void kernel_launch(void* const* d_in, const int* in_sizes, int n_in,
                              void* d_out, int out_size)
{
    const float* x     = (const float*)d_in[0];
    const int*   erow  = (const int*)  d_in[1];
    const int*   ecol  = (const int*)  d_in[2];
    const float* eval  = (const float*)d_in[3];
    const float* W1    = (const float*)d_in[4];
    const float* b1    = (const float*)d_in[5];
    const float* W2    = (const float*)d_in[6];
    const float* b2    = (const float*)d_in[7];
    const float* Wout  = (const float*)d_in[8];
    const float* bout  = (const float*)d_in[9];
    float* out = (float*)d_out;

    const int M  = in_sizes[0] / D;     // 100000
    const int nE = in_sizes[1];         // 1600000

    float *tvec;
    __half *bufH1, *bufH2;
    int *cnt, *rowptr, *cursor, *bsum;
    int2* epack;
    cudaGetSymbolAddress((void**)&bufH1,  g_bufH1);
    cudaGetSymbolAddress((void**)&bufH2,  g_bufH2);
    cudaGetSymbolAddress((void**)&tvec,   g_t);
    cudaGetSymbolAddress((void**)&cnt,    g_cnt);
    cudaGetSymbolAddress((void**)&rowptr, g_rowptr);
    cudaGetSymbolAddress((void**)&cursor, g_cursor);
    cudaGetSymbolAddress((void**)&epack,  g_epack);
    cudaGetSymbolAddress((void**)&bsum,   g_bsum);

    cudaFuncSetAttribute(gemm_mma_kernel<float>,
                         cudaFuncAttributeMaxDynamicSharedMemorySize, SM_GEMM);
    cudaFuncSetAttribute(gemm_mma_kernel<__half>,
                         cudaFuncAttributeMaxDynamicSharedMemorySize, SM_GEMM);

    const int nb = (M + 1023) / 1024;                // 98
    const int spmmBlocks = (M * 32 + 255) / 256;
    const int tileBlocks = (M + 127) / 128;
    const int rowBlocks  = (M + 255) / 256;

    // Prep weights + zero counters (one combined launch)
    prep_zero_kernel<<<130, 256>>>(W1, W2, cnt, M);

    // CSR build
    hist_kernel<<<1024, 256>>>(erow, cnt, nE);
    scan1_kernel<<<nb, 1024>>>(cnt, cnt, bsum, M);
    scan2_kernel<<<1, 128>>>(bsum, nb);
    scan3_kernel<<<256, 256>>>(cnt, bsum, rowptr, cursor, M, nE);
    scatter_kernel<<<1024, 256>>>(erow, ecol, eval, cursor, epack, nE);

    // Layer 1: h1 = relu(A @ fp16(x @ W1) + b1)
    gemm_mma_kernel<float><<<tileBlocks, 256, SM_GEMM>>>(x, 0, bufH1, M);
    spmm_csr_h_bias_relu_kernel<<<spmmBlocks, 256>>>(rowptr, epack, bufH1, b1, bufH2, M);

    // Layer 2 + head GEMV fused: t = relu(A @ fp16(h1 @ W2) + b2) . Wout
    gemm_mma_kernel<__half><<<tileBlocks, 256, SM_GEMM>>>(bufH2, 1, bufH1, M);
    spmm_csr_relu_gemv_kernel<<<spmmBlocks, 256>>>(rowptr, epack, bufH1, b2, Wout, tvec, M);

    // out = softplus(A @ t + bout)
    spmm_csr_scalar_softplus_kernel<<<rowBlocks, 256>>>(rowptr, epack, tvec, bout, out, M);
}

// round 16
// speedup vs baseline: 2.9629x; 1.0548x over previous
#include <cuda_runtime.h>
#include <cuda_bf16.h>
#include <cuda_fp16.h>
#include <math.h>
#include <stdint.h>

#define N_MAX 100000
#define E_MAX 1600000
#define D 128
#define WP 136                      // padded pitch (bf16 elems) for mma tiles

// Scratch (static __device__ per allocation rules)
__device__ __half g_bufH1[(size_t)N_MAX * D];        // fp16 GEMM output (XW)
__device__ __half g_bufH2[(size_t)N_MAX * D];        // fp16 hidden state h1
__device__ float g_t[N_MAX];                         // fused head output
__device__ int   g_cnt[N_MAX];
__device__ int   g_rowptr[N_MAX + 1];
__device__ int   g_cursor[N_MAX];
__device__ __align__(16) int2 g_epack[E_MAX];        // packed (col, val)
__device__ int   g_bsum[256];
// Pre-split weights, transposed Bt[n][k], padded pitch WP (bf16 hi/lo)
__device__ unsigned short g_w_hi[2][128 * WP];
__device__ unsigned short g_w_lo[2][128 * WP];

// ===========================================================================
// Weight prep (runs on side stream, overlapped with CSR build)
// ===========================================================================
__global__ void prep_w_kernel(const float* __restrict__ W1,
                              const float* __restrict__ W2) {
    const float* W = (blockIdx.x == 0) ? W1 : W2;
    unsigned short* hi = g_w_hi[blockIdx.x];
    unsigned short* lo = g_w_lo[blockIdx.x];
    for (int idx = threadIdx.x; idx < 128 * 128; idx += blockDim.x) {
        int k = idx >> 7, nn = idx & 127;
        float w = W[idx];
        __nv_bfloat16 h = __float2bfloat16_rn(w);
        float wl = w - __bfloat162float(h);
        hi[nn * WP + k] = __bfloat16_as_ushort(h);
        lo[nn * WP + k] = __bfloat16_as_ushort(__float2bfloat16_rn(wl));
    }
}

__global__ void zero_int_kernel(int* __restrict__ p, int n) {
    int i = blockIdx.x * blockDim.x + threadIdx.x;
    int stride = gridDim.x * blockDim.x;
    for (; i < n; i += stride) p[i] = 0;
}

// ===========================================================================
// GEMM: C16[M,128] = fp16( A[M,128] @ W )  via split-bf16 mma.sync (bf16x3)
// ===========================================================================
#define SA_HI 0
#define SA_LO (128 * WP * 2)
#define SB_HI (2 * 128 * WP * 2)
#define SB_LO (3 * 128 * WP * 2)
#define SM_GEMM (4 * 128 * WP * 2)     // 139264 B

__device__ __forceinline__ float2 load2(const float* p) {
    return *reinterpret_cast<const float2*>(p);
}
__device__ __forceinline__ float2 load2(const __half* p) {
    return __half22float2(*reinterpret_cast<const __half2*>(p));
}

#define MMA_BF16(c, a, b) \
    asm volatile( \
        "mma.sync.aligned.m16n8k16.row.col.f32.bf16.bf16.f32 " \
        "{%0,%1,%2,%3}, {%4,%5,%6,%7}, {%8,%9}, {%0,%1,%2,%3};" \
        : "+f"((c)[0]), "+f"((c)[1]), "+f"((c)[2]), "+f"((c)[3]) \
        : "r"((a)[0]), "r"((a)[1]), "r"((a)[2]), "r"((a)[3]), \
          "r"((b)[0]), "r"((b)[1]))

template<typename TIN>
__global__ __launch_bounds__(256) void gemm_mma_kernel(
    const TIN* __restrict__ A, int widx, __half* __restrict__ C16, int M)
{
    extern __shared__ char smem[];
    const int tid = threadIdx.x;
    const int wid = tid >> 5, lane = tid & 31;
    const int row0 = blockIdx.x * 128;

    {
        const uint4* whi = reinterpret_cast<const uint4*>(g_w_hi[widx]);
        const uint4* wlo = reinterpret_cast<const uint4*>(g_w_lo[widx]);
        uint4* dh = reinterpret_cast<uint4*>(smem + SB_HI);
        uint4* dl = reinterpret_cast<uint4*>(smem + SB_LO);
        for (int i = tid; i < (128 * WP * 2) / 16; i += 256) {
            dh[i] = whi[i];
            dl[i] = wlo[i];
        }
    }
    {
        unsigned short* sAhi = reinterpret_cast<unsigned short*>(smem + SA_HI);
        unsigned short* sAlo = reinterpret_cast<unsigned short*>(smem + SA_LO);
        for (int idx = tid; idx < 128 * 64; idx += 256) {
            int row = idx >> 6;
            int cp  = (idx & 63) << 1;
            int gr  = row0 + row;
            float2 a = make_float2(0.f, 0.f);
            if (gr < M)
                a = load2(A + (size_t)gr * D + cp);
            __nv_bfloat16 h0 = __float2bfloat16_rn(a.x);
            __nv_bfloat16 h1 = __float2bfloat16_rn(a.y);
            __nv_bfloat16 l0 = __float2bfloat16_rn(a.x - __bfloat162float(h0));
            __nv_bfloat16 l1 = __float2bfloat16_rn(a.y - __bfloat162float(h1));
            int o = row * WP + cp;
            *reinterpret_cast<uint32_t*>(sAhi + o) =
                (uint32_t)__bfloat16_as_ushort(h0) |
                ((uint32_t)__bfloat16_as_ushort(h1) << 16);
            *reinterpret_cast<uint32_t*>(sAlo + o) =
                (uint32_t)__bfloat16_as_ushort(l0) |
                ((uint32_t)__bfloat16_as_ushort(l1) << 16);
        }
    }
    __syncthreads();

    const int wm = (wid & 3) * 32;
    const int wn = (wid >> 2) * 64;
    const int qr = lane >> 2;
    const int qc = (lane & 3) * 2;

    const uint32_t* pAh = reinterpret_cast<const uint32_t*>(smem + SA_HI);
    const uint32_t* pAl = reinterpret_cast<const uint32_t*>(smem + SA_LO);
    const uint32_t* pBh = reinterpret_cast<const uint32_t*>(smem + SB_HI);
    const uint32_t* pBl = reinterpret_cast<const uint32_t*>(smem + SB_LO);
    const int WPW = WP / 2;

    float acc[2][8][4];
    #pragma unroll
    for (int mt = 0; mt < 2; mt++)
        #pragma unroll
        for (int nt = 0; nt < 8; nt++)
            #pragma unroll
            for (int j = 0; j < 4; j++) acc[mt][nt][j] = 0.f;

    #pragma unroll
    for (int ks = 0; ks < 8; ks++) {
        const int kw = (ks * 16 + qc) >> 1;
        uint32_t ah[2][4], al[2][4];
        #pragma unroll
        for (int mt = 0; mt < 2; mt++) {
            int r = wm + mt * 16 + qr;
            int w0 = r * WPW + kw;
            int w1 = (r + 8) * WPW + kw;
            ah[mt][0] = pAh[w0];     ah[mt][1] = pAh[w1];
            ah[mt][2] = pAh[w0 + 4]; ah[mt][3] = pAh[w1 + 4];
            al[mt][0] = pAl[w0];     al[mt][1] = pAl[w1];
            al[mt][2] = pAl[w0 + 4]; al[mt][3] = pAl[w1 + 4];
        }
        uint32_t bh[8][2], bl[8][2];
        #pragma unroll
        for (int nt = 0; nt < 8; nt++) {
            int n = wn + nt * 8 + qr;
            int w0 = n * WPW + kw;
            bh[nt][0] = pBh[w0]; bh[nt][1] = pBh[w0 + 4];
            bl[nt][0] = pBl[w0]; bl[nt][1] = pBl[w0 + 4];
        }
        #pragma unroll
        for (int mt = 0; mt < 2; mt++)
            #pragma unroll
            for (int nt = 0; nt < 8; nt++) {
                MMA_BF16(acc[mt][nt], ah[mt], bh[nt]);
                MMA_BF16(acc[mt][nt], ah[mt], bl[nt]);
                MMA_BF16(acc[mt][nt], al[mt], bh[nt]);
            }
    }

    #pragma unroll
    for (int mt = 0; mt < 2; mt++) {
        int r = row0 + wm + mt * 16 + qr;
        #pragma unroll
        for (int nt = 0; nt < 8; nt++) {
            int col = wn + nt * 8 + qc;
            if (r < M)
                *reinterpret_cast<__half2*>(C16 + (size_t)r * D + col) =
                    __floats2half2_rn(acc[mt][nt][0], acc[mt][nt][1]);
            if (r + 8 < M)
                *reinterpret_cast<__half2*>(C16 + (size_t)(r + 8) * D + col) =
                    __floats2half2_rn(acc[mt][nt][2], acc[mt][nt][3]);
        }
    }
}

// ===========================================================================
// CSR build
// ===========================================================================
__global__ void hist_kernel(const int* __restrict__ erow, int* __restrict__ cnt, int nE) {
    int i = blockIdx.x * blockDim.x + threadIdx.x;
    int stride = gridDim.x * blockDim.x;
    for (; i < nE; i += stride) atomicAdd(&cnt[erow[i]], 1);
}

// Two-level shfl scan (2 syncs): exclusive partials + block sums
__global__ __launch_bounds__(1024) void scan1_kernel(
    const int* __restrict__ cnt, int* __restrict__ excl, int* __restrict__ bsum, int n)
{
    __shared__ int wsum[32];
    int tid = threadIdx.x;
    int lane = tid & 31, wid = tid >> 5;
    int i = blockIdx.x * 1024 + tid;
    int v = (i < n) ? cnt[i] : 0;
    int s = v;
    #pragma unroll
    for (int o = 1; o < 32; o <<= 1) {
        int t = __shfl_up_sync(0xFFFFFFFFu, s, o);
        if (lane >= o) s += t;
    }
    if (lane == 31) wsum[wid] = s;
    __syncthreads();
    if (wid == 0) {
        int w = wsum[lane];
        #pragma unroll
        for (int o = 1; o < 32; o <<= 1) {
            int t = __shfl_up_sync(0xFFFFFFFFu, w, o);
            if (lane >= o) w += t;
        }
        wsum[lane] = w;
    }
    __syncthreads();
    int incl = s + (wid > 0 ? wsum[wid - 1] : 0);
    if (i < n) excl[i] = incl - v;
    if (tid == 1023) bsum[blockIdx.x] = incl;
}

// Combine with INLINE exclusive scan of bsum (nb <= 128) — replaces scan2.
__global__ __launch_bounds__(256) void scan3_kernel(
    const int* __restrict__ excl, const int* __restrict__ bsum,
    int* __restrict__ rowptr, int* __restrict__ cursor, int n, int nE, int nb)
{
    __shared__ int sbs[128];
    __shared__ int wpre[4];
    int tid = threadIdx.x;
    int lane = tid & 31, wid = tid >> 5;
    int v = 0, s = 0;
    if (tid < 128) {
        v = (tid < nb) ? bsum[tid] : 0;
        s = v;
        #pragma unroll
        for (int o = 1; o < 32; o <<= 1) {
            int t = __shfl_up_sync(0xFFFFFFFFu, s, o);
            if (lane >= o) s += t;
        }
        if (lane == 31) wpre[wid] = s;
    }
    __syncthreads();
    if (tid < 128) {
        int base = 0;
        #pragma unroll
        for (int k = 0; k < 4; k++)
            if (k < wid) base += wpre[k];
        sbs[tid] = base + s - v;           // exclusive block prefix
    }
    __syncthreads();

    int i = blockIdx.x * blockDim.x + tid;
    int stride = gridDim.x * blockDim.x;
    for (; i <= n; i += stride) {
        if (i < n) {
            int rp = excl[i] + sbs[i >> 10];
            rowptr[i] = rp;
            cursor[i] = rp;
        } else {
            rowptr[n] = nE;
        }
    }
}

__global__ void scatter_kernel(
    const int* __restrict__ erow, const int* __restrict__ ecol,
    const float* __restrict__ eval, int* __restrict__ cursor,
    int2* __restrict__ epack, int nE)
{
    int i = blockIdx.x * blockDim.x + threadIdx.x;
    int stride = gridDim.x * blockDim.x;
    for (; i < nE; i += stride) {
        int r = erow[i];
        int pos = atomicAdd(&cursor[r], 1);
        epack[pos] = make_int2(ecol[i], __float_as_int(eval[i]));
    }
}

// ===========================================================================
// SpMM core: fp16 gathers, fp32 accumulate. One warp per row, 4 cols/lane.
// ===========================================================================
#define SPMM_FMA(acc, v, g) do { \
    float2 _a01 = __half22float2(*reinterpret_cast<__half2*>(&(g).x)); \
    float2 _a23 = __half22float2(*reinterpret_cast<__half2*>(&(g).y)); \
    (acc).x = fmaf((v), _a01.x, (acc).x); (acc).y = fmaf((v), _a01.y, (acc).y); \
    (acc).z = fmaf((v), _a23.x, (acc).z); (acc).w = fmaf((v), _a23.y, (acc).w); \
} while (0)

__device__ __forceinline__ float4 spmm_row_acc(
    const int2* __restrict__ epack, const __half* __restrict__ X,
    int beg, int end, int lane)
{
    float4 acc = make_float4(0.f, 0.f, 0.f, 0.f);
    int i = beg;
    if ((i & 1) && i < end) {                     // peel to 16B alignment
        int2 e = epack[i];
        uint2 g = *reinterpret_cast<const uint2*>(X + (size_t)e.x * D + lane * 4);
        SPMM_FMA(acc, __int_as_float(e.y), g);
        i++;
    }
    for (; i + 8 <= end; i += 8) {
        int4 ep0 = *reinterpret_cast<const int4*>(epack + i);
        int4 ep1 = *reinterpret_cast<const int4*>(epack + i + 2);
        int4 ep2 = *reinterpret_cast<const int4*>(epack + i + 4);
        int4 ep3 = *reinterpret_cast<const int4*>(epack + i + 6);
        uint2 g[8];
        g[0] = *reinterpret_cast<const uint2*>(X + (size_t)ep0.x * D + lane * 4);
        g[1] = *reinterpret_cast<const uint2*>(X + (size_t)ep0.z * D + lane * 4);
        g[2] = *reinterpret_cast<const uint2*>(X + (size_t)ep1.x * D + lane * 4);
        g[3] = *reinterpret_cast<const uint2*>(X + (size_t)ep1.z * D + lane * 4);
        g[4] = *reinterpret_cast<const uint2*>(X + (size_t)ep2.x * D + lane * 4);
        g[5] = *reinterpret_cast<const uint2*>(X + (size_t)ep2.z * D + lane * 4);
        g[6] = *reinterpret_cast<const uint2*>(X + (size_t)ep3.x * D + lane * 4);
        g[7] = *reinterpret_cast<const uint2*>(X + (size_t)ep3.z * D + lane * 4);
        SPMM_FMA(acc, __int_as_float(ep0.y), g[0]);
        SPMM_FMA(acc, __int_as_float(ep0.w), g[1]);
        SPMM_FMA(acc, __int_as_float(ep1.y), g[2]);
        SPMM_FMA(acc, __int_as_float(ep1.w), g[3]);
        SPMM_FMA(acc, __int_as_float(ep2.y), g[4]);
        SPMM_FMA(acc, __int_as_float(ep2.w), g[5]);
        SPMM_FMA(acc, __int_as_float(ep3.y), g[6]);
        SPMM_FMA(acc, __int_as_float(ep3.w), g[7]);
    }
    for (; i + 2 <= end; i += 2) {
        int4 ep = *reinterpret_cast<const int4*>(epack + i);
        uint2 g0 = *reinterpret_cast<const uint2*>(X + (size_t)ep.x * D + lane * 4);
        uint2 g1 = *reinterpret_cast<const uint2*>(X + (size_t)ep.z * D + lane * 4);
        SPMM_FMA(acc, __int_as_float(ep.y), g0);
        SPMM_FMA(acc, __int_as_float(ep.w), g1);
    }
    if (i < end) {
        int2 e = epack[i];
        uint2 g = *reinterpret_cast<const uint2*>(X + (size_t)e.x * D + lane * 4);
        SPMM_FMA(acc, __int_as_float(e.y), g);
    }
    return acc;
}

// Layer-1 SpMM: out = fp16(relu(A@X + bias))
__global__ __launch_bounds__(256) void spmm_csr_h_bias_relu_kernel(
    const int* __restrict__ rowptr, const int2* __restrict__ epack,
    const __half* __restrict__ X,
    const float* __restrict__ bias, __half* __restrict__ out, int M)
{
    int gt = blockIdx.x * blockDim.x + threadIdx.x;
    int r = gt >> 5;
    int lane = gt & 31;
    if (r >= M) return;

    float4 acc = spmm_row_acc(epack, X, rowptr[r], rowptr[r + 1], lane);

    const float4 b = *reinterpret_cast<const float4*>(bias + lane * 4);
    __half2 o01 = __floats2half2_rn(fmaxf(acc.x + b.x, 0.f), fmaxf(acc.y + b.y, 0.f));
    __half2 o23 = __floats2half2_rn(fmaxf(acc.z + b.z, 0.f), fmaxf(acc.w + b.w, 0.f));
    uint2 ov;
    ov.x = *reinterpret_cast<uint32_t*>(&o01);
    ov.y = *reinterpret_cast<uint32_t*>(&o23);
    *reinterpret_cast<uint2*>(out + (size_t)r * D + lane * 4) = ov;
}

// Layer-2 SpMM with fused head GEMV: t[r] = dot(relu(A@X + bias), Wout)
__global__ __launch_bounds__(256) void spmm_csr_relu_gemv_kernel(
    const int* __restrict__ rowptr, const int2* __restrict__ epack,
    const __half* __restrict__ X,
    const float* __restrict__ bias, const float* __restrict__ Wout,
    float* __restrict__ t, int M)
{
    int gt = blockIdx.x * blockDim.x + threadIdx.x;
    int r = gt >> 5;
    int lane = gt & 31;
    if (r >= M) return;

    float4 acc = spmm_row_acc(epack, X, rowptr[r], rowptr[r + 1], lane);

    const float4 b = *reinterpret_cast<const float4*>(bias + lane * 4);
    const float4 w = *reinterpret_cast<const float4*>(Wout + lane * 4);
    float s = fmaxf(acc.x + b.x, 0.f) * w.x
            + fmaxf(acc.y + b.y, 0.f) * w.y
            + fmaxf(acc.z + b.z, 0.f) * w.z
            + fmaxf(acc.w + b.w, 0.f) * w.w;
    #pragma unroll
    for (int o = 16; o > 0; o >>= 1)
        s += __shfl_xor_sync(0xFFFFFFFFu, s, o);
    if (lane == 0) t[r] = s;
}

// ---------------------------------------------------------------------------
// Scalar CSR SpMM + softplus
// ---------------------------------------------------------------------------
__global__ __launch_bounds__(256) void spmm_csr_scalar_softplus_kernel(
    const int* __restrict__ rowptr, const int2* __restrict__ epack,
    const float* __restrict__ t,
    const float* __restrict__ bout, float* __restrict__ out, int M)
{
    int r = blockIdx.x * blockDim.x + threadIdx.x;
    if (r >= M) return;
    int beg = rowptr[r], end = rowptr[r + 1];
    float acc = 0.f;
    for (int i = beg; i < end; i++) {
        int2 e = epack[i];
        acc = fmaf(__int_as_float(e.y), t[e.x], acc);
    }
    float s = acc + bout[0];
    out[r] = fmaxf(s, 0.f) + log1pf(expf(-fabsf(s)));
}

// ===========================================================================
// Launch — CSR build on main stream, prep_w+gemm1 forked onto a side stream
// (graph-capture-safe fork/join via events on cudaStreamPerThread).
// ===========================================================================
extern "C" void kernel_launch(void* const* d_in, const int* in_sizes, int n_in,
                              void* d_out, int out_size)
{
    const float* x     = (const float*)d_in[0];
    const int*   erow  = (const int*)  d_in[1];
    const int*   ecol  = (const int*)  d_in[2];
    const float* eval  = (const float*)d_in[3];
    const float* W1    = (const float*)d_in[4];
    const float* b1    = (const float*)d_in[5];
    const float* W2    = (const float*)d_in[6];
    const float* b2    = (const float*)d_in[7];
    const float* Wout  = (const float*)d_in[8];
    const float* bout  = (const float*)d_in[9];
    float* out = (float*)d_out;

    const int M  = in_sizes[0] / D;     // 100000
    const int nE = in_sizes[1];         // 1600000

    float *tvec;
    __half *bufH1, *bufH2;
    int *cnt, *rowptr, *cursor, *bsum;
    int2* epack;
    cudaGetSymbolAddress((void**)&bufH1,  g_bufH1);
    cudaGetSymbolAddress((void**)&bufH2,  g_bufH2);
    cudaGetSymbolAddress((void**)&tvec,   g_t);
    cudaGetSymbolAddress((void**)&cnt,    g_cnt);
    cudaGetSymbolAddress((void**)&rowptr, g_rowptr);
    cudaGetSymbolAddress((void**)&cursor, g_cursor);
    cudaGetSymbolAddress((void**)&epack,  g_epack);
    cudaGetSymbolAddress((void**)&bsum,   g_bsum);

    cudaFuncSetAttribute(gemm_mma_kernel<float>,
                         cudaFuncAttributeMaxDynamicSharedMemorySize, SM_GEMM);
    cudaFuncSetAttribute(gemm_mma_kernel<__half>,
                         cudaFuncAttributeMaxDynamicSharedMemorySize, SM_GEMM);

    const int nb = (M + 1023) / 1024;                // 98
    const int spmmBlocks = (M * 32 + 255) / 256;
    const int tileBlocks = (M + 127) / 128;
    const int rowBlocks  = (M + 255) / 256;

    cudaStream_t ms = cudaStreamPerThread;
    cudaStream_t side;
    cudaStreamCreateWithFlags(&side, cudaStreamNonBlocking);
    cudaEvent_t evFork, evJoin;
    cudaEventCreateWithFlags(&evFork, cudaEventDisableTiming);
    cudaEventCreateWithFlags(&evJoin, cudaEventDisableTiming);

    // Fork: side stream runs weight prep + gemm1 (independent of CSR build)
    cudaEventRecord(evFork, ms);
    cudaStreamWaitEvent(side, evFork, 0);
    prep_w_kernel<<<2, 256, 0, side>>>(W1, W2);
    gemm_mma_kernel<float><<<tileBlocks, 256, SM_GEMM, side>>>(x, 0, bufH1, M);
    cudaEventRecord(evJoin, side);

    // Main stream: CSR build
    zero_int_kernel<<<128, 256, 0, ms>>>(cnt, M);
    hist_kernel<<<1024, 256, 0, ms>>>(erow, cnt, nE);
    scan1_kernel<<<nb, 1024, 0, ms>>>(cnt, cnt, bsum, M);
    scan3_kernel<<<256, 256, 0, ms>>>(cnt, bsum, rowptr, cursor, M, nE, nb);
    scatter_kernel<<<1024, 256, 0, ms>>>(erow, ecol, eval, cursor, epack, nE);

    // Join: spmm1 needs both CSR and gemm1 output
    cudaStreamWaitEvent(ms, evJoin, 0);

    // Layer 1: h1 = relu(A @ fp16(x @ W1) + b1)
    spmm_csr_h_bias_relu_kernel<<<spmmBlocks, 256, 0, ms>>>(rowptr, epack, bufH1, b1, bufH2, M);

    // Layer 2 + head GEMV fused: t = relu(A @ fp16(h1 @ W2) + b2) . Wout
    gemm_mma_kernel<__half><<<tileBlocks, 256, SM_GEMM, ms>>>(bufH2, 1, bufH1, M);
    spmm_csr_relu_gemv_kernel<<<spmmBlocks, 256, 0, ms>>>(rowptr, epack, bufH1, b2, Wout, tvec, M);

    // out = softplus(A @ t + bout)
    spmm_csr_scalar_softplus_kernel<<<rowBlocks, 256, 0, ms>>>(rowptr, epack, tvec, bout, out, M);

    cudaEventDestroy(evFork);
    cudaEventDestroy(evJoin);
    cudaStreamDestroy(side);
}